// round 1
// baseline (speedup 1.0000x reference)
#include <cuda_runtime.h>
#include <math.h>

#define SEQ    1024
#define DIMM   1024
#define NHEADS 16
#define FFD    4096
#define NBATCH 2
#define NTOK   (NBATCH*SEQ)
#define NDEPTH 6

// ---------------- scratch (allocation-free: __device__ globals) ----------------
__device__ float g_h[NTOK*DIMM];                              //   8 MB
__device__ float g_qkv[NTOK*3*DIMM];                          //  24 MB
__device__ float g_scores[(size_t)NBATCH*NHEADS*SEQ*SEQ];     // 128 MB
__device__ float g_o[NTOK*DIMM];                              //   8 MB
__device__ float g_ffn[NTOK*FFD];                             //  32 MB

// ---------------- block reductions (blockDim.x == 256) ----------------
__device__ __forceinline__ float blockReduceSum(float val, float* sh){
  #pragma unroll
  for(int o=16;o>0;o>>=1) val += __shfl_xor_sync(0xffffffffu, val, o);
  int wid = threadIdx.x>>5;
  __syncthreads();
  if((threadIdx.x&31)==0) sh[wid]=val;
  __syncthreads();
  float r = 0.f;
  #pragma unroll
  for(int w=0;w<8;w++) r += sh[w];
  return r;
}

__device__ __forceinline__ float blockReduceMax(float val, float* sh){
  #pragma unroll
  for(int o=16;o>0;o>>=1) val = fmaxf(val, __shfl_xor_sync(0xffffffffu, val, o));
  int wid = threadIdx.x>>5;
  __syncthreads();
  if((threadIdx.x&31)==0) sh[wid]=val;
  __syncthreads();
  float r = sh[0];
  #pragma unroll
  for(int w=1;w<8;w++) r = fmaxf(r, sh[w]);
  return r;
}

// ---------------- copy x -> out buffer ----------------
__global__ void copy_kernel(const float* __restrict__ src, float* __restrict__ dst, int n){
  int i = blockIdx.x*blockDim.x + threadIdx.x;
  if(i<n) dst[i]=src[i];
}

// ---------------- LayerNorm: one block per row of 1024 ----------------
__global__ void layernorm_kernel(const float* __restrict__ x, const float* __restrict__ g,
                                 const float* __restrict__ beta, float* __restrict__ out){
  __shared__ float sh[8];
  int row = blockIdx.x, t = threadIdx.x;
  const float4* xr = (const float4*)(x + (size_t)row*DIMM);
  float4 v = xr[t];
  float s = v.x+v.y+v.z+v.w;
  s = blockReduceSum(s, sh);
  float mu = s * (1.f/DIMM);
  float dx=v.x-mu, dy=v.y-mu, dz=v.z-mu, dw=v.w-mu;
  float ss = dx*dx+dy*dy+dz*dz+dw*dw;
  ss = blockReduceSum(ss, sh);
  float rinv = rsqrtf(ss*(1.f/DIMM) + 1e-5f);
  const float4 gg = ((const float4*)g)[t];
  const float4 bb = ((const float4*)beta)[t];
  float4 o;
  o.x = dx*rinv*gg.x + bb.x;
  o.y = dy*rinv*gg.y + bb.y;
  o.z = dz*rinv*gg.z + bb.z;
  o.w = dw*rinv*gg.w + bb.w;
  ((float4*)(out + (size_t)row*DIMM))[t] = o;
}

// ---------------- SGEMM: C[M,N] = A[M,K] @ B[K,N] (+epilogue) ----------------
// 128x128 tile, BK=8, 8x8 microtile, 256 threads. All dims multiples of tile.
// EPI: 0 = none, 1 = +bias +residual, 2 = +bias then exact GELU
template<int EPI>
__global__ void __launch_bounds__(256)
sgemm_kernel(const float* __restrict__ A, const float* __restrict__ B,
             const float* __restrict__ bias, const float* __restrict__ res,
             float* __restrict__ C, int M, int N, int K){
  __shared__ float As[8][128];
  __shared__ float Bs[8][128];
  int t  = threadIdx.x;
  int bx = blockIdx.x;   // N tile
  int by = blockIdx.y;   // M tile
  const float* Ab = A + (size_t)by*128*K;
  const float* Bb = B + (size_t)bx*128;
  int arow = t>>1,  acol = (t&1)*4;     // A: 128 rows x 8 k
  int brow = t>>5,  bcol = (t&31)*4;    // B: 8 k x 128 cols
  int ty = (t>>4)*8, tx = (t&15)*8;
  float acc[8][8];
  #pragma unroll
  for(int i=0;i<8;i++)
    #pragma unroll
    for(int j=0;j<8;j++) acc[i][j]=0.f;

  for(int k0=0;k0<K;k0+=8){
    float4 a4 = *(const float4*)(Ab + (size_t)arow*K + k0 + acol);
    As[acol+0][arow]=a4.x; As[acol+1][arow]=a4.y;
    As[acol+2][arow]=a4.z; As[acol+3][arow]=a4.w;
    float4 b4 = *(const float4*)(Bb + (size_t)(k0+brow)*N + bcol);
    *(float4*)&Bs[brow][bcol] = b4;
    __syncthreads();
    #pragma unroll
    for(int k=0;k<8;k++){
      float4 a0 = *(const float4*)&As[k][ty];
      float4 a1 = *(const float4*)&As[k][ty+4];
      float4 b0 = *(const float4*)&Bs[k][tx];
      float4 b1 = *(const float4*)&Bs[k][tx+4];
      float ar[8]={a0.x,a0.y,a0.z,a0.w,a1.x,a1.y,a1.z,a1.w};
      float br[8]={b0.x,b0.y,b0.z,b0.w,b1.x,b1.y,b1.z,b1.w};
      #pragma unroll
      for(int i=0;i<8;i++)
        #pragma unroll
        for(int j=0;j<8;j++) acc[i][j] = fmaf(ar[i], br[j], acc[i][j]);
    }
    __syncthreads();
  }

  #pragma unroll
  for(int i=0;i<8;i++){
    int row = by*128 + ty + i;
    #pragma unroll
    for(int j=0;j<8;j+=4){
      int col = bx*128 + tx + j;
      float4 v;
      v.x=acc[i][j]; v.y=acc[i][j+1]; v.z=acc[i][j+2]; v.w=acc[i][j+3];
      if(EPI>=1){
        const float4 bb = *(const float4*)(bias + col);
        v.x+=bb.x; v.y+=bb.y; v.z+=bb.z; v.w+=bb.w;
      }
      if(EPI==2){ // exact GELU: 0.5*x*(1+erf(x/sqrt(2)))
        v.x = 0.5f*v.x*(1.f+erff(v.x*0.70710678118654752f));
        v.y = 0.5f*v.y*(1.f+erff(v.y*0.70710678118654752f));
        v.z = 0.5f*v.z*(1.f+erff(v.z*0.70710678118654752f));
        v.w = 0.5f*v.w*(1.f+erff(v.w*0.70710678118654752f));
      }
      if(EPI==1){
        const float4 rr = *(const float4*)(res + (size_t)row*N + col);
        v.x+=rr.x; v.y+=rr.y; v.z+=rr.z; v.w+=rr.w;
      }
      *(float4*)(C + (size_t)row*N + col) = v;
    }
  }
}

// ---------------- scores: S[b,h,i,j] = (Q.K^T)*scale + rpb[h,i,j] ----------------
// grid: (16 j-tiles, 16 i-tiles, 32 bh); 64x64 tile, 4x4 microtile, 256 threads
__global__ void __launch_bounds__(256)
scores_kernel(const float* __restrict__ qkv, const float* __restrict__ rpb,
              float* __restrict__ S){
  __shared__ float Qs[64][68];  // [d][i]
  __shared__ float Ks[64][68];  // [d][j]
  int t  = threadIdx.x;
  int jt = blockIdx.x, it = blockIdx.y, bh = blockIdx.z;
  int b = bh>>4, h = bh&15;
  const float* Qb = qkv + (size_t)b*SEQ*(3*DIMM) + h*64;
  const float* Kb = Qb + DIMM;
  #pragma unroll
  for(int u=0;u<4;u++){
    int lin = t + u*256;
    int r = lin>>4;          // local row
    int c = (lin&15)*4;      // d offset
    float4 q = *(const float4*)(Qb + (size_t)(it*64+r)*(3*DIMM) + c);
    Qs[c+0][r]=q.x; Qs[c+1][r]=q.y; Qs[c+2][r]=q.z; Qs[c+3][r]=q.w;
    float4 k = *(const float4*)(Kb + (size_t)(jt*64+r)*(3*DIMM) + c);
    Ks[c+0][r]=k.x; Ks[c+1][r]=k.y; Ks[c+2][r]=k.z; Ks[c+3][r]=k.w;
  }
  __syncthreads();
  int ty = (t>>4)*4, tx = (t&15)*4;
  float acc[4][4];
  #pragma unroll
  for(int i=0;i<4;i++)
    #pragma unroll
    for(int j=0;j<4;j++) acc[i][j]=0.f;
  #pragma unroll
  for(int d=0;d<64;d++){
    float4 a = *(const float4*)&Qs[d][ty];
    float4 c = *(const float4*)&Ks[d][tx];
    float ar[4]={a.x,a.y,a.z,a.w}, cr[4]={c.x,c.y,c.z,c.w};
    #pragma unroll
    for(int i=0;i<4;i++)
      #pragma unroll
      for(int j=0;j<4;j++) acc[i][j]=fmaf(ar[i],cr[j],acc[i][j]);
  }
  const float scale = 0.125f;  // dh=64 -> 64^-0.5
  #pragma unroll
  for(int i=0;i<4;i++){
    int gi = it*64+ty+i;
    const float4 rb = *(const float4*)(rpb + ((size_t)h*SEQ+gi)*SEQ + jt*64+tx);
    float4 v;
    v.x=fmaf(acc[i][0],scale,rb.x);
    v.y=fmaf(acc[i][1],scale,rb.y);
    v.z=fmaf(acc[i][2],scale,rb.z);
    v.w=fmaf(acc[i][3],scale,rb.w);
    *(float4*)(S + ((size_t)bh*SEQ+gi)*SEQ + jt*64+tx) = v;
  }
}

// ---------------- row softmax over 1024, in-place ----------------
__global__ void softmax_kernel(float* __restrict__ S){
  __shared__ float sh[8];
  float4* p = (float4*)(S + (size_t)blockIdx.x*SEQ);
  int t = threadIdx.x;
  float4 v = p[t];
  float m = fmaxf(fmaxf(v.x,v.y), fmaxf(v.z,v.w));
  m = blockReduceMax(m, sh);
  v.x=__expf(v.x-m); v.y=__expf(v.y-m); v.z=__expf(v.z-m); v.w=__expf(v.w-m);
  float s = v.x+v.y+v.z+v.w;
  s = blockReduceSum(s, sh);
  float r = 1.f/s;
  v.x*=r; v.y*=r; v.z*=r; v.w*=r;
  p[t]=v;
}

// ---------------- O = P @ V, written as [token, h*64+d] ----------------
// grid: (16 i-tiles, 32 bh); 64(rows) x 64(dh) output per block
__global__ void __launch_bounds__(256)
attnv_kernel(const float* __restrict__ S, const float* __restrict__ qkv,
             float* __restrict__ O){
  __shared__ float Ps[64][68];  // [j][i]
  __shared__ float Vs[64][68];  // [j][d]
  int t  = threadIdx.x;
  int it = blockIdx.x, bh = blockIdx.y;
  int b = bh>>4, h = bh&15;
  const float* Sb = S + ((size_t)bh*SEQ + it*64)*SEQ;
  const float* Vb = qkv + (size_t)b*SEQ*(3*DIMM) + 2*DIMM + h*64;
  int ty=(t>>4)*4, tx=(t&15)*4;
  float acc[4][4];
  #pragma unroll
  for(int i=0;i<4;i++)
    #pragma unroll
    for(int j=0;j<4;j++) acc[i][j]=0.f;

  for(int j0=0;j0<SEQ;j0+=64){
    #pragma unroll
    for(int u=0;u<4;u++){
      int lin=t+u*256;
      int r=lin>>4;
      int c=(lin&15)*4;
      float4 p = *(const float4*)(Sb + (size_t)r*SEQ + j0 + c);
      Ps[c+0][r]=p.x; Ps[c+1][r]=p.y; Ps[c+2][r]=p.z; Ps[c+3][r]=p.w;
      float4 v = *(const float4*)(Vb + (size_t)(j0+r)*(3*DIMM) + c);
      *(float4*)&Vs[r][c] = v;
    }
    __syncthreads();
    #pragma unroll
    for(int j=0;j<64;j++){
      float4 a = *(const float4*)&Ps[j][ty];
      float4 c = *(const float4*)&Vs[j][tx];
      float ar[4]={a.x,a.y,a.z,a.w}, cr[4]={c.x,c.y,c.z,c.w};
      #pragma unroll
      for(int i=0;i<4;i++)
        #pragma unroll
        for(int jj=0;jj<4;jj++) acc[i][jj]=fmaf(ar[i],cr[jj],acc[i][jj]);
    }
    __syncthreads();
  }
  #pragma unroll
  for(int i=0;i<4;i++){
    int gi = it*64+ty+i;
    float4 v; v.x=acc[i][0]; v.y=acc[i][1]; v.z=acc[i][2]; v.w=acc[i][3];
    *(float4*)(O + (size_t)(b*SEQ+gi)*DIMM + h*64 + tx) = v;
  }
}

// ---------------- driver ----------------
extern "C" void kernel_launch(void* const* d_in, const int* in_sizes, int n_in,
                              void* d_out, int out_size){
  const float* x     =(const float*)d_in[0];
  const float* rpb   =(const float*)d_in[1];
  const float* ln1_g =(const float*)d_in[2];
  const float* ln1_b =(const float*)d_in[3];
  const float* w_qkv =(const float*)d_in[4];
  const float* w_out =(const float*)d_in[5];
  const float* b_out =(const float*)d_in[6];
  const float* ln2_g =(const float*)d_in[7];
  const float* ln2_b =(const float*)d_in[8];
  const float* w1    =(const float*)d_in[9];
  const float* b1    =(const float*)d_in[10];
  const float* w2    =(const float*)d_in[11];
  const float* b2    =(const float*)d_in[12];
  float* X = (float*)d_out;   // running activation buffer == output

  float *h, *qkv, *sc, *o, *ff;
  cudaGetSymbolAddress((void**)&h,   g_h);
  cudaGetSymbolAddress((void**)&qkv, g_qkv);
  cudaGetSymbolAddress((void**)&sc,  g_scores);
  cudaGetSymbolAddress((void**)&o,   g_o);
  cudaGetSymbolAddress((void**)&ff,  g_ffn);

  copy_kernel<<<(NTOK*DIMM+255)/256, 256>>>(x, X, NTOK*DIMM);

  for(int l=0;l<NDEPTH;l++){
    // ---- attention block ----
    layernorm_kernel<<<NTOK,256>>>(X, ln1_g + l*DIMM, ln1_b + l*DIMM, h);
    sgemm_kernel<0><<<dim3(24,16),256>>>(h, w_qkv + (size_t)l*DIMM*3*DIMM,
                                         nullptr, nullptr, qkv, NTOK, 3*DIMM, DIMM);
    scores_kernel<<<dim3(16,16,NBATCH*NHEADS),256>>>(qkv, rpb, sc);
    softmax_kernel<<<NBATCH*NHEADS*SEQ,256>>>(sc);
    attnv_kernel<<<dim3(16,NBATCH*NHEADS),256>>>(sc, qkv, o);
    sgemm_kernel<1><<<dim3(8,16),256>>>(o, w_out + (size_t)l*DIMM*DIMM,
                                        b_out + l*DIMM, X, X, NTOK, DIMM, DIMM);
    // ---- FFN block ----
    layernorm_kernel<<<NTOK,256>>>(X, ln2_g + l*DIMM, ln2_b + l*DIMM, h);
    sgemm_kernel<2><<<dim3(32,16),256>>>(h, w1 + (size_t)l*DIMM*FFD,
                                         b1 + l*FFD, nullptr, ff, NTOK, FFD, DIMM);
    sgemm_kernel<1><<<dim3(8,16),256>>>(ff, w2 + (size_t)l*FFD*DIMM,
                                        b2 + l*DIMM, X, X, NTOK, DIMM, FFD);
  }
}

// round 2
// speedup vs baseline: 3.0578x; 3.0578x over previous
#include <cuda_runtime.h>
#include <math.h>

#define SEQ    1024
#define DIMM   1024
#define NHEADS 16
#define FFD    4096
#define NBATCH 2
#define NTOK   (NBATCH*SEQ)
#define NDEPTH 6

// ---------------- scratch (allocation-free: __device__ globals) ----------------
__device__ float g_h[NTOK*DIMM];                              //   8 MB
__device__ float g_qkv[NTOK*3*DIMM];                          //  24 MB
__device__ float g_scores[(size_t)NBATCH*NHEADS*SEQ*SEQ];     // 128 MB
__device__ float g_kt[(size_t)NBATCH*NHEADS*64*SEQ];          //   8 MB
__device__ float g_o[NTOK*DIMM];                              //   8 MB
__device__ float g_ffn[NTOK*FFD];                             //  32 MB

// ---------------- helpers ----------------
__device__ __forceinline__ float to_tf32(float x){
  asm("cvt.rna.tf32.f32 %0, %0;" : "+f"(x));
  return x;
}

__device__ __forceinline__ void mma8(float* d, const float* a, const float* b){
  asm volatile("mma.sync.aligned.m16n8k8.row.col.f32.tf32.tf32.f32 "
    "{%0,%1,%2,%3}, {%4,%5,%6,%7}, {%8,%9}, {%0,%1,%2,%3};\n"
    : "+f"(d[0]),"+f"(d[1]),"+f"(d[2]),"+f"(d[3])
    : "r"(__float_as_uint(a[0])),"r"(__float_as_uint(a[1])),
      "r"(__float_as_uint(a[2])),"r"(__float_as_uint(a[3])),
      "r"(__float_as_uint(b[0])),"r"(__float_as_uint(b[1])));
}

// ---------------- block reductions (blockDim.x == 256) ----------------
__device__ __forceinline__ float blockReduceSum(float val, float* sh){
  #pragma unroll
  for(int o=16;o>0;o>>=1) val += __shfl_xor_sync(0xffffffffu, val, o);
  int wid = threadIdx.x>>5;
  __syncthreads();
  if((threadIdx.x&31)==0) sh[wid]=val;
  __syncthreads();
  float r = 0.f;
  #pragma unroll
  for(int w=0;w<8;w++) r += sh[w];
  return r;
}

__device__ __forceinline__ float blockReduceMax(float val, float* sh){
  #pragma unroll
  for(int o=16;o>0;o>>=1) val = fmaxf(val, __shfl_xor_sync(0xffffffffu, val, o));
  int wid = threadIdx.x>>5;
  __syncthreads();
  if((threadIdx.x&31)==0) sh[wid]=val;
  __syncthreads();
  float r = sh[0];
  #pragma unroll
  for(int w=1;w<8;w++) r = fmaxf(r, sh[w]);
  return r;
}

// ---------------- copy x -> out buffer ----------------
__global__ void copy_kernel(const float* __restrict__ src, float* __restrict__ dst, int n){
  int i = blockIdx.x*blockDim.x + threadIdx.x;
  if(i<n) dst[i]=src[i];
}

// ---------------- LayerNorm: one block per row of 1024 ----------------
__global__ void layernorm_kernel(const float* __restrict__ x, const float* __restrict__ g,
                                 const float* __restrict__ beta, float* __restrict__ out){
  __shared__ float sh[8];
  int row = blockIdx.x, t = threadIdx.x;
  const float4* xr = (const float4*)(x + (size_t)row*DIMM);
  float4 v = xr[t];
  float s = v.x+v.y+v.z+v.w;
  s = blockReduceSum(s, sh);
  float mu = s * (1.f/DIMM);
  float dx=v.x-mu, dy=v.y-mu, dz=v.z-mu, dw=v.w-mu;
  float ss = dx*dx+dy*dy+dz*dz+dw*dw;
  ss = blockReduceSum(ss, sh);
  float rinv = rsqrtf(ss*(1.f/DIMM) + 1e-5f);
  const float4 gg = ((const float4*)g)[t];
  const float4 bb = ((const float4*)beta)[t];
  float4 o;
  o.x = dx*rinv*gg.x + bb.x;
  o.y = dy*rinv*gg.y + bb.y;
  o.z = dz*rinv*gg.z + bb.z;
  o.w = dw*rinv*gg.w + bb.w;
  ((float4*)(out + (size_t)row*DIMM))[t] = o;
}

// ---------------- transpose K into [bh][d][j] for scores GEMM ----------------
__global__ void transpose_k(const float* __restrict__ qkv, float* __restrict__ kt){
  __shared__ float tile[64][68];
  int bh=blockIdx.y, b=bh>>4, h=bh&15;
  int j0=blockIdx.x*64;
  const float* src = qkv + (size_t)b*SEQ*(3*DIMM) + DIMM + h*64;
  int t=threadIdx.x;
  #pragma unroll
  for(int i=0;i<4;i++){
    int idx=t+256*i;                 // 0..1023
    int j=idx>>4, c=(idx&15)<<2;
    float4 v=*(const float4*)(src + (size_t)(j0+j)*(3*DIMM) + c);
    tile[c+0][j]=v.x; tile[c+1][j]=v.y; tile[c+2][j]=v.z; tile[c+3][j]=v.w;
  }
  __syncthreads();
  float* dst = kt + (size_t)bh*64*SEQ + j0;
  #pragma unroll
  for(int i=0;i<4;i++){
    int idx=t+256*i;
    int d=idx>>4, c=(idx&15)<<2;
    *(float4*)(dst + (size_t)d*SEQ + c) = *(float4*)&tile[d][c];
  }
}

// ---------------- TF32 tensor-core GEMM ----------------
// C[M,N] = A[M,K] @ B[K,N] (+ epilogue), batched over blockIdx.z via strides.
// Per-z offset = (z>>4)*s?b + (z&15)*s?h  (set sb=16*sh for uniform batches).
// EPI: 0=none, 1=+bias+res, 2=gelu(+bias), 3=*0.125 + rpb[z&15]
// BN: 128 (8 warps as 2x4, warp tile 64x32) or 64 (8 warps as 4x2, warp tile 32x32)
template<int EPI, int BN>
__global__ void __launch_bounds__(256)
gemm_tf32(const float* __restrict__ A, int lda, size_t sAb, size_t sAh,
          const float* __restrict__ B, int ldb, size_t sBb, size_t sBh,
          float* __restrict__ C, int ldc, size_t sCb, size_t sCh,
          const float* __restrict__ P1, size_t sP1h,
          const float* __restrict__ P2,
          int M, int N, int K)
{
  constexpr int BM=128, BK=32;
  constexpr int WN=(BN==128)?4:2;
  constexpr int WM=8/WN;
  constexpr int WTM=BM/WM, WTN=BN/WN;
  constexpr int MT=WTM/16, NT=WTN/8;
  constexpr int PB=BN+8;
  constexpr int BITER=BN/32;

  __shared__ float As[BM][36];   // [m][k], pad 36 -> conflict-free frag loads
  __shared__ float Bs[BK][PB];   // [k][n], pad +8 -> conflict-free frag loads

  int z=blockIdx.z, zb=z>>4, zh=z&15;
  A += (size_t)zb*sAb + (size_t)zh*sAh;
  B += (size_t)zb*sBb + (size_t)zh*sBh;
  C += (size_t)zb*sCb + (size_t)zh*sCh;
  const float* R1 = P1 + (size_t)zh*sP1h;

  int t=threadIdx.x;
  const float* Ag = A + (size_t)blockIdx.y*BM*lda;
  const float* Bg = B + blockIdx.x*BN;

  // prefetch tile k0 = 0
  float4 pa[4]; float4 pb[BITER];
  #pragma unroll
  for(int i=0;i<4;i++){
    int idx=t+256*i;
    pa[i]=*(const float4*)(Ag + (size_t)(idx>>3)*lda + ((idx&7)<<2));
  }
  #pragma unroll
  for(int i=0;i<BITER;i++){
    int idx=t+256*i;
    int kk=(BN==128)?(idx>>5):(idx>>4);
    int cc=(BN==128)?(idx&31):(idx&15);
    pb[i]=*(const float4*)(Bg + (size_t)kk*ldb + (cc<<2));
  }

  float acc[MT][NT][4];
  #pragma unroll
  for(int i=0;i<MT;i++)
    #pragma unroll
    for(int j=0;j<NT;j++)
      #pragma unroll
      for(int r=0;r<4;r++) acc[i][j][r]=0.f;

  int wid=t>>5, lane=t&31;
  int wm=wid/WN, wn=wid%WN;
  int m0=wm*WTM, n0=wn*WTN;
  int qr=lane>>2, rr=lane&3;

  for(int k0=0;k0<K;k0+=BK){
    __syncthreads();
    #pragma unroll
    for(int i=0;i<4;i++){
      int idx=t+256*i; int m=idx>>3, c=(idx&7)<<2;
      float4 v;
      v.x=to_tf32(pa[i].x); v.y=to_tf32(pa[i].y);
      v.z=to_tf32(pa[i].z); v.w=to_tf32(pa[i].w);
      *(float4*)&As[m][c]=v;
    }
    #pragma unroll
    for(int i=0;i<BITER;i++){
      int idx=t+256*i;
      int kk=(BN==128)?(idx>>5):(idx>>4);
      int cc=((BN==128)?(idx&31):(idx&15))<<2;
      float4 v;
      v.x=to_tf32(pb[i].x); v.y=to_tf32(pb[i].y);
      v.z=to_tf32(pb[i].z); v.w=to_tf32(pb[i].w);
      *(float4*)&Bs[kk][cc]=v;
    }
    __syncthreads();
    if(k0+BK<K){  // prefetch next tile; LDG overlaps the MMA chain below
      const float* Ag2 = Ag + k0 + BK;
      #pragma unroll
      for(int i=0;i<4;i++){
        int idx=t+256*i;
        pa[i]=*(const float4*)(Ag2 + (size_t)(idx>>3)*lda + ((idx&7)<<2));
      }
      const float* Bg2 = Bg + (size_t)(k0+BK)*ldb;
      #pragma unroll
      for(int i=0;i<BITER;i++){
        int idx=t+256*i;
        int kk=(BN==128)?(idx>>5):(idx>>4);
        int cc=(BN==128)?(idx&31):(idx&15);
        pb[i]=*(const float4*)(Bg2 + (size_t)kk*ldb + (cc<<2));
      }
    }
    #pragma unroll
    for(int ks=0;ks<4;ks++){
      int kk=ks*8;
      float a[MT][4], b[NT][2];
      #pragma unroll
      for(int mt=0;mt<MT;mt++){
        int r=m0+mt*16+qr;
        a[mt][0]=As[r  ][kk+rr];
        a[mt][1]=As[r+8][kk+rr];
        a[mt][2]=As[r  ][kk+rr+4];
        a[mt][3]=As[r+8][kk+rr+4];
      }
      #pragma unroll
      for(int nt=0;nt<NT;nt++){
        int cn=n0+nt*8+qr;
        b[nt][0]=Bs[kk+rr  ][cn];
        b[nt][1]=Bs[kk+rr+4][cn];
      }
      #pragma unroll
      for(int mt=0;mt<MT;mt++)
        #pragma unroll
        for(int nt=0;nt<NT;nt++)
          mma8(acc[mt][nt], a[mt], b[nt]);
    }
  }

  // ---------------- epilogue ----------------
  int brow = blockIdx.y*BM + m0 + qr;
  int bcol = blockIdx.x*BN + n0 + (rr<<1);
  #pragma unroll
  for(int mt=0;mt<MT;mt++){
    #pragma unroll
    for(int nt=0;nt<NT;nt++){
      int col = bcol + nt*8;
      #pragma unroll
      for(int hh=0;hh<2;hh++){
        int row = brow + mt*16 + hh*8;
        float vx = acc[mt][nt][2*hh+0];
        float vy = acc[mt][nt][2*hh+1];
        if(EPI==1||EPI==2){ vx += P1[col]; vy += P1[col+1]; }
        if(EPI==2){
          vx = 0.5f*vx*(1.f+erff(vx*0.70710678118654752f));
          vy = 0.5f*vy*(1.f+erff(vy*0.70710678118654752f));
        }
        if(EPI==1){
          vx += P2[(size_t)row*ldc+col];
          vy += P2[(size_t)row*ldc+col+1];
        }
        if(EPI==3){
          vx = fmaf(vx,0.125f,R1[(size_t)row*ldc+col]);
          vy = fmaf(vy,0.125f,R1[(size_t)row*ldc+col+1]);
        }
        float2 o; o.x=vx; o.y=vy;
        *(float2*)(C + (size_t)row*ldc + col) = o;
      }
    }
  }
}

// ---------------- row softmax over 1024, in-place ----------------
__global__ void softmax_kernel(float* __restrict__ S){
  __shared__ float sh[8];
  float4* p = (float4*)(S + (size_t)blockIdx.x*SEQ);
  int t = threadIdx.x;
  float4 v = p[t];
  float m = fmaxf(fmaxf(v.x,v.y), fmaxf(v.z,v.w));
  m = blockReduceMax(m, sh);
  v.x=__expf(v.x-m); v.y=__expf(v.y-m); v.z=__expf(v.z-m); v.w=__expf(v.w-m);
  float s = v.x+v.y+v.z+v.w;
  s = blockReduceSum(s, sh);
  float r = 1.f/s;
  v.x*=r; v.y*=r; v.z*=r; v.w*=r;
  p[t]=v;
}

// ---------------- driver ----------------
extern "C" void kernel_launch(void* const* d_in, const int* in_sizes, int n_in,
                              void* d_out, int out_size){
  const float* x     =(const float*)d_in[0];
  const float* rpb   =(const float*)d_in[1];
  const float* ln1_g =(const float*)d_in[2];
  const float* ln1_b =(const float*)d_in[3];
  const float* w_qkv =(const float*)d_in[4];
  const float* w_out =(const float*)d_in[5];
  const float* b_out =(const float*)d_in[6];
  const float* ln2_g =(const float*)d_in[7];
  const float* ln2_b =(const float*)d_in[8];
  const float* w1    =(const float*)d_in[9];
  const float* b1    =(const float*)d_in[10];
  const float* w2    =(const float*)d_in[11];
  const float* b2    =(const float*)d_in[12];
  float* X = (float*)d_out;   // running activation buffer == output

  float *h, *qkv, *sc, *kt, *o, *ff;
  cudaGetSymbolAddress((void**)&h,   g_h);
  cudaGetSymbolAddress((void**)&qkv, g_qkv);
  cudaGetSymbolAddress((void**)&sc,  g_scores);
  cudaGetSymbolAddress((void**)&kt,  g_kt);
  cudaGetSymbolAddress((void**)&o,   g_o);
  cudaGetSymbolAddress((void**)&ff,  g_ffn);

  copy_kernel<<<(NTOK*DIMM+255)/256, 256>>>(x, X, NTOK*DIMM);

  const size_t SS = (size_t)SEQ*SEQ;

  for(int l=0;l<NDEPTH;l++){
    // ---- attention block ----
    layernorm_kernel<<<NTOK,256>>>(X, ln1_g + l*DIMM, ln1_b + l*DIMM, h);
    // qkv = h @ w_qkv   [2048 x 3072]
    gemm_tf32<0,128><<<dim3(24,16,1),256>>>(
        h, DIMM, 0,0,
        w_qkv + (size_t)l*DIMM*3*DIMM, 3*DIMM, 0,0,
        qkv, 3*DIMM, 0,0,
        nullptr, 0, nullptr,
        NTOK, 3*DIMM, DIMM);
    // K^T scratch [bh][d][j]
    transpose_k<<<dim3(16,32),256>>>(qkv, kt);
    // scores = Q K^T * 0.125 + rpb  per bh
    gemm_tf32<3,128><<<dim3(8,8,32),256>>>(
        qkv, 3*DIMM, (size_t)SEQ*3*DIMM, 64,
        kt, SEQ, (size_t)16*64*SEQ, (size_t)64*SEQ,
        sc, SEQ, (size_t)16*SS, SS,
        rpb, SS, nullptr,
        SEQ, SEQ, 64);
    softmax_kernel<<<NBATCH*NHEADS*SEQ,256>>>(sc);
    // o = P @ V  per bh, written as [token, h*64+d]
    gemm_tf32<0,64><<<dim3(1,8,32),256>>>(
        sc, SEQ, (size_t)16*SS, SS,
        qkv + 2*DIMM, 3*DIMM, (size_t)SEQ*3*DIMM, 64,
        o, DIMM, (size_t)SEQ*DIMM, 64,
        nullptr, 0, nullptr,
        SEQ, 64, SEQ);
    // X += o @ w_out + b_out
    gemm_tf32<1,128><<<dim3(8,16,1),256>>>(
        o, DIMM, 0,0,
        w_out + (size_t)l*DIMM*DIMM, DIMM, 0,0,
        X, DIMM, 0,0,
        b_out + l*DIMM, 0, X,
        NTOK, DIMM, DIMM);
    // ---- FFN block ----
    layernorm_kernel<<<NTOK,256>>>(X, ln2_g + l*DIMM, ln2_b + l*DIMM, h);
    gemm_tf32<2,128><<<dim3(32,16,1),256>>>(
        h, DIMM, 0,0,
        w1 + (size_t)l*DIMM*FFD, FFD, 0,0,
        ff, FFD, 0,0,
        b1 + l*FFD, 0, nullptr,
        NTOK, FFD, DIMM);
    gemm_tf32<1,128><<<dim3(8,16,1),256>>>(
        ff, FFD, 0,0,
        w2 + (size_t)l*FFD*DIMM, DIMM, 0,0,
        X, DIMM, 0,0,
        b2 + l*DIMM, 0, X,
        NTOK, DIMM, FFD);
  }
}

// round 4
// speedup vs baseline: 3.3296x; 1.0889x over previous
#include <cuda_runtime.h>
#include <math.h>
#include <stdint.h>

#define SEQ    1024
#define DIMM   1024
#define NHEADS 16
#define FFD    4096
#define NBATCH 2
#define NTOK   (NBATCH*SEQ)
#define NDEPTH 6

// ---------------- scratch (allocation-free: __device__ globals) ----------------
__device__ float g_h[NTOK*DIMM];                              //   8 MB
__device__ float g_qkv[NTOK*3*DIMM];                          //  24 MB
__device__ float g_o[NTOK*DIMM];                              //   8 MB
__device__ float g_ffn[NTOK*FFD];                             //  32 MB

// ---------------- helpers ----------------
__device__ __forceinline__ float to_tf32(float x){
  asm("cvt.rna.tf32.f32 %0, %0;" : "+f"(x));
  return x;
}

__device__ __forceinline__ void mma8(float* d, const float* a, const float* b){
  asm volatile("mma.sync.aligned.m16n8k8.row.col.f32.tf32.tf32.f32 "
    "{%0,%1,%2,%3}, {%4,%5,%6,%7}, {%8,%9}, {%0,%1,%2,%3};\n"
    : "+f"(d[0]),"+f"(d[1]),"+f"(d[2]),"+f"(d[3])
    : "r"(__float_as_uint(a[0])),"r"(__float_as_uint(a[1])),
      "r"(__float_as_uint(a[2])),"r"(__float_as_uint(a[3])),
      "r"(__float_as_uint(b[0])),"r"(__float_as_uint(b[1])));
}

// ---------------- block reductions (blockDim.x == 256) ----------------
__device__ __forceinline__ float blockReduceSum(float val, float* sh){
  #pragma unroll
  for(int o=16;o>0;o>>=1) val += __shfl_xor_sync(0xffffffffu, val, o);
  int wid = threadIdx.x>>5;
  __syncthreads();
  if((threadIdx.x&31)==0) sh[wid]=val;
  __syncthreads();
  float r = 0.f;
  #pragma unroll
  for(int w=0;w<8;w++) r += sh[w];
  return r;
}

// ---------------- small kernels ----------------
__global__ void copy_kernel(const float* __restrict__ src, float* __restrict__ dst, int n){
  int i = blockIdx.x*blockDim.x + threadIdx.x;
  if(i<n) dst[i]=src[i];
}

__global__ void layernorm_kernel(const float* __restrict__ x, const float* __restrict__ g,
                                 const float* __restrict__ beta, float* __restrict__ out){
  __shared__ float sh[8];
  int row = blockIdx.x, t = threadIdx.x;
  const float4* xr = (const float4*)(x + (size_t)row*DIMM);
  float4 v = xr[t];
  float s = v.x+v.y+v.z+v.w;
  s = blockReduceSum(s, sh);
  float mu = s * (1.f/DIMM);
  float dx=v.x-mu, dy=v.y-mu, dz=v.z-mu, dw=v.w-mu;
  float ss = dx*dx+dy*dy+dz*dz+dw*dw;
  ss = blockReduceSum(ss, sh);
  float rinv = rsqrtf(ss*(1.f/DIMM) + 1e-5f);
  const float4 gg = ((const float4*)g)[t];
  const float4 bb = ((const float4*)beta)[t];
  float4 o;
  o.x = dx*rinv*gg.x + bb.x;
  o.y = dy*rinv*gg.y + bb.y;
  o.z = dz*rinv*gg.z + bb.z;
  o.w = dw*rinv*gg.w + bb.w;
  ((float4*)(out + (size_t)row*DIMM))[t] = o;
}

// ---------------- mma.sync TF32 GEMM (dense) ----------------
// C[M,N] = A[M,K] @ B[K,N] (+ epilogue). EPI: 0=none, 1=+bias+res, 2=gelu(+bias)
template<int EPI>
__global__ void __launch_bounds__(256)
gemm_tf32(const float* __restrict__ A, int lda,
          const float* __restrict__ B, int ldb,
          float* __restrict__ C, int ldc,
          const float* __restrict__ bias, const float* __restrict__ res,
          int M, int N, int K)
{
  constexpr int BM=128, BN=128, BK=32;
  constexpr int MT=4, NT=4;   // 2x4 warps, warp tile 64x32
  __shared__ float As[BM][36];
  __shared__ float Bs[BK][BN+8];

  int t=threadIdx.x;
  const float* Ag = A + (size_t)blockIdx.y*BM*lda;
  const float* Bg = B + blockIdx.x*BN;

  float4 pa[4]; float4 pb[4];
  #pragma unroll
  for(int i=0;i<4;i++){
    int idx=t+256*i;
    pa[i]=*(const float4*)(Ag + (size_t)(idx>>3)*lda + ((idx&7)<<2));
  }
  #pragma unroll
  for(int i=0;i<4;i++){
    int idx=t+256*i;
    pb[i]=*(const float4*)(Bg + (size_t)(idx>>5)*ldb + ((idx&31)<<2));
  }

  float acc[MT][NT][4];
  #pragma unroll
  for(int i=0;i<MT;i++)
    #pragma unroll
    for(int j=0;j<NT;j++)
      #pragma unroll
      for(int r=0;r<4;r++) acc[i][j][r]=0.f;

  int wid=t>>5, lane=t&31;
  int wm=wid>>2, wn=wid&3;
  int m0=wm*64, n0=wn*32;
  int qr=lane>>2, rr=lane&3;

  for(int k0=0;k0<K;k0+=BK){
    __syncthreads();
    #pragma unroll
    for(int i=0;i<4;i++){
      int idx=t+256*i; int m=idx>>3, c=(idx&7)<<2;
      float4 v;
      v.x=to_tf32(pa[i].x); v.y=to_tf32(pa[i].y);
      v.z=to_tf32(pa[i].z); v.w=to_tf32(pa[i].w);
      *(float4*)&As[m][c]=v;
    }
    #pragma unroll
    for(int i=0;i<4;i++){
      int idx=t+256*i; int kk=idx>>5, cc=(idx&31)<<2;
      float4 v;
      v.x=to_tf32(pb[i].x); v.y=to_tf32(pb[i].y);
      v.z=to_tf32(pb[i].z); v.w=to_tf32(pb[i].w);
      *(float4*)&Bs[kk][cc]=v;
    }
    __syncthreads();
    if(k0+BK<K){
      const float* Ag2 = Ag + k0 + BK;
      #pragma unroll
      for(int i=0;i<4;i++){
        int idx=t+256*i;
        pa[i]=*(const float4*)(Ag2 + (size_t)(idx>>3)*lda + ((idx&7)<<2));
      }
      const float* Bg2 = Bg + (size_t)(k0+BK)*ldb;
      #pragma unroll
      for(int i=0;i<4;i++){
        int idx=t+256*i;
        pb[i]=*(const float4*)(Bg2 + (size_t)(idx>>5)*ldb + ((idx&31)<<2));
      }
    }
    #pragma unroll
    for(int ks=0;ks<4;ks++){
      int kk=ks*8;
      float a[MT][4], b[NT][2];
      #pragma unroll
      for(int mt=0;mt<MT;mt++){
        int r=m0+mt*16+qr;
        a[mt][0]=As[r  ][kk+rr];
        a[mt][1]=As[r+8][kk+rr];
        a[mt][2]=As[r  ][kk+rr+4];
        a[mt][3]=As[r+8][kk+rr+4];
      }
      #pragma unroll
      for(int nt=0;nt<NT;nt++){
        int cn=n0+nt*8+qr;
        b[nt][0]=Bs[kk+rr  ][cn];
        b[nt][1]=Bs[kk+rr+4][cn];
      }
      #pragma unroll
      for(int mt=0;mt<MT;mt++)
        #pragma unroll
        for(int nt=0;nt<NT;nt++)
          mma8(acc[mt][nt], a[mt], b[nt]);
    }
  }

  int brow = blockIdx.y*BM + m0 + qr;
  int bcol = blockIdx.x*BN + n0 + (rr<<1);
  #pragma unroll
  for(int mt=0;mt<MT;mt++){
    #pragma unroll
    for(int nt=0;nt<NT;nt++){
      int col = bcol + nt*8;
      #pragma unroll
      for(int hh=0;hh<2;hh++){
        int row = brow + mt*16 + hh*8;
        float vx = acc[mt][nt][2*hh+0];
        float vy = acc[mt][nt][2*hh+1];
        if(EPI==1||EPI==2){ vx += bias[col]; vy += bias[col+1]; }
        if(EPI==2){
          vx = 0.5f*vx*(1.f+erff(vx*0.70710678118654752f));
          vy = 0.5f*vy*(1.f+erff(vy*0.70710678118654752f));
        }
        if(EPI==1){
          vx += res[(size_t)row*ldc+col];
          vy += res[(size_t)row*ldc+col+1];
        }
        float2 o; o.x=vx; o.y=vy;
        *(float2*)(C + (size_t)row*ldc + col) = o;
      }
    }
  }
}

// ---------------- fused flash attention ----------------
// grid (16 i-tiles, 32 bh), 128 threads (4 warps). 64-row Q tile per block.
// S = Q K^T * 0.125 + rpb;  online softmax;  O = P V / l.  Scores never hit gmem.
#define PAD_P 68
#define PAD_K 68
#define PAD_V 72
#define FA_SMEM ((64*PAD_P + 64*PAD_K + 64*PAD_V)*4)

__global__ void __launch_bounds__(128)
attn_flash(const float* __restrict__ qkv, const float* __restrict__ rpb,
           float* __restrict__ O)
{
  extern __shared__ float fsm[];
  float* Ps = fsm;                       // [64][PAD_P]  (Q staging, then P)
  float* Ks = fsm + 64*PAD_P;            // [64][PAD_K]  [j][d]
  float* Vs = fsm + 64*(PAD_P+PAD_K);    // [64][PAD_V]  [j][d]

  int t = threadIdx.x, lane = t&31, w = t>>5;
  int qr = lane>>2, rr = lane&3;
  int it = blockIdx.x, bh = blockIdx.y;
  int b = bh>>4, h = bh&15;
  const float* Qg = qkv + (size_t)(b*SEQ + it*64)*(3*DIMM) + h*64;
  const float* Kg = qkv + (size_t)b*SEQ*(3*DIMM) + DIMM   + h*64;
  const float* Vg = qkv + (size_t)b*SEQ*(3*DIMM) + 2*DIMM + h*64;
  const float* Rg = rpb + ((size_t)h*SEQ + it*64)*SEQ;

  // ---- stage Q, pull A-fragments to registers ----
  #pragma unroll
  for(int u=0;u<8;u++){
    int idx = t + 128*u;                // 0..1023
    int r = idx>>4, c = (idx&15)<<2;
    float4 v = *(const float4*)(Qg + (size_t)r*(3*DIMM) + c);
    v.x=to_tf32(v.x); v.y=to_tf32(v.y); v.z=to_tf32(v.z); v.w=to_tf32(v.w);
    *(float4*)(Ps + r*PAD_P + c) = v;
  }
  __syncthreads();
  int m0 = w*16;
  float qf[8][4];
  #pragma unroll
  for(int kk=0;kk<8;kk++){
    qf[kk][0]=Ps[(m0+qr  )*PAD_P + kk*8+rr];
    qf[kk][1]=Ps[(m0+qr+8)*PAD_P + kk*8+rr];
    qf[kk][2]=Ps[(m0+qr  )*PAD_P + kk*8+rr+4];
    qf[kk][3]=Ps[(m0+qr+8)*PAD_P + kk*8+rr+4];
  }
  __syncthreads();

  float oacc[8][4];
  #pragma unroll
  for(int nf=0;nf<8;nf++)
    #pragma unroll
    for(int r=0;r<4;r++) oacc[nf][r]=0.f;
  float mrow0=-1e30f, mrow1=-1e30f, lrow0=0.f, lrow1=0.f;

  for(int j0=0;j0<SEQ;j0+=64){
    // ---- fill K/V tiles ----
    #pragma unroll
    for(int u=0;u<8;u++){
      int idx = t + 128*u;
      int r = idx>>4, c = (idx&15)<<2;
      float4 kv = *(const float4*)(Kg + (size_t)(j0+r)*(3*DIMM) + c);
      kv.x=to_tf32(kv.x); kv.y=to_tf32(kv.y); kv.z=to_tf32(kv.z); kv.w=to_tf32(kv.w);
      *(float4*)(Ks + r*PAD_K + c) = kv;
      float4 vv = *(const float4*)(Vg + (size_t)(j0+r)*(3*DIMM) + c);
      vv.x=to_tf32(vv.x); vv.y=to_tf32(vv.y); vv.z=to_tf32(vv.z); vv.w=to_tf32(vv.w);
      *(float4*)(Vs + r*PAD_V + c) = vv;
    }
    __syncthreads();

    // ---- S = Q K^T ----
    float s[8][4];
    #pragma unroll
    for(int nf=0;nf<8;nf++)
      #pragma unroll
      for(int r=0;r<4;r++) s[nf][r]=0.f;
    #pragma unroll
    for(int kk=0;kk<8;kk++){
      float bf[8][2];
      #pragma unroll
      for(int nf=0;nf<8;nf++){
        bf[nf][0]=Ks[(nf*8+qr)*PAD_K + kk*8+rr];
        bf[nf][1]=Ks[(nf*8+qr)*PAD_K + kk*8+rr+4];
      }
      #pragma unroll
      for(int nf=0;nf<8;nf++) mma8(s[nf], qf[kk], bf[nf]);
    }
    // ---- scale + rpb ----
    #pragma unroll
    for(int nf=0;nf<8;nf++){
      const float* rp = Rg + (size_t)(m0+qr)*SEQ + j0 + nf*8 + 2*rr;
      float2 r0 = *(const float2*)rp;
      float2 r1 = *(const float2*)(rp + 8*SEQ);
      s[nf][0]=fmaf(s[nf][0],0.125f,r0.x);
      s[nf][1]=fmaf(s[nf][1],0.125f,r0.y);
      s[nf][2]=fmaf(s[nf][2],0.125f,r1.x);
      s[nf][3]=fmaf(s[nf][3],0.125f,r1.y);
    }
    // ---- online softmax ----
    float mx0=-1e30f, mx1=-1e30f;
    #pragma unroll
    for(int nf=0;nf<8;nf++){
      mx0=fmaxf(mx0,fmaxf(s[nf][0],s[nf][1]));
      mx1=fmaxf(mx1,fmaxf(s[nf][2],s[nf][3]));
    }
    mx0=fmaxf(mx0,__shfl_xor_sync(0xffffffffu,mx0,1));
    mx0=fmaxf(mx0,__shfl_xor_sync(0xffffffffu,mx0,2));
    mx1=fmaxf(mx1,__shfl_xor_sync(0xffffffffu,mx1,1));
    mx1=fmaxf(mx1,__shfl_xor_sync(0xffffffffu,mx1,2));
    float mn0=fmaxf(mrow0,mx0), mn1=fmaxf(mrow1,mx1);
    float a0=__expf(mrow0-mn0), a1=__expf(mrow1-mn1);
    mrow0=mn0; mrow1=mn1;
    float sum0=0.f, sum1=0.f;
    #pragma unroll
    for(int nf=0;nf<8;nf++){
      s[nf][0]=__expf(s[nf][0]-mn0); s[nf][1]=__expf(s[nf][1]-mn0);
      s[nf][2]=__expf(s[nf][2]-mn1); s[nf][3]=__expf(s[nf][3]-mn1);
      sum0 += s[nf][0]+s[nf][1];
      sum1 += s[nf][2]+s[nf][3];
    }
    sum0 += __shfl_xor_sync(0xffffffffu,sum0,1);
    sum0 += __shfl_xor_sync(0xffffffffu,sum0,2);
    sum1 += __shfl_xor_sync(0xffffffffu,sum1,1);
    sum1 += __shfl_xor_sync(0xffffffffu,sum1,2);
    lrow0 = lrow0*a0 + sum0;
    lrow1 = lrow1*a1 + sum1;
    #pragma unroll
    for(int nf=0;nf<8;nf++){
      oacc[nf][0]*=a0; oacc[nf][1]*=a0;
      oacc[nf][2]*=a1; oacc[nf][3]*=a1;
    }
    // ---- stage P (tf32) ----
    #pragma unroll
    for(int nf=0;nf<8;nf++){
      Ps[(m0+qr  )*PAD_P + nf*8+2*rr  ]=to_tf32(s[nf][0]);
      Ps[(m0+qr  )*PAD_P + nf*8+2*rr+1]=to_tf32(s[nf][1]);
      Ps[(m0+qr+8)*PAD_P + nf*8+2*rr  ]=to_tf32(s[nf][2]);
      Ps[(m0+qr+8)*PAD_P + nf*8+2*rr+1]=to_tf32(s[nf][3]);
    }
    __syncwarp();
    // ---- O += P V ----
    #pragma unroll
    for(int kk=0;kk<8;kk++){
      float af[4];
      af[0]=Ps[(m0+qr  )*PAD_P + kk*8+rr];
      af[1]=Ps[(m0+qr+8)*PAD_P + kk*8+rr];
      af[2]=Ps[(m0+qr  )*PAD_P + kk*8+rr+4];
      af[3]=Ps[(m0+qr+8)*PAD_P + kk*8+rr+4];
      #pragma unroll
      for(int nf=0;nf<8;nf++){
        float bf2[2];
        bf2[0]=Vs[(kk*8+rr  )*PAD_V + nf*8+qr];
        bf2[1]=Vs[(kk*8+rr+4)*PAD_V + nf*8+qr];
        mma8(oacc[nf], af, bf2);
      }
    }
    __syncthreads();
  }

  // ---- epilogue: O / l ----
  float inv0=1.f/lrow0, inv1=1.f/lrow1;
  float* Ob = O + (size_t)(b*SEQ + it*64)*DIMM + h*64;
  #pragma unroll
  for(int nf=0;nf<8;nf++){
    float2 o0; o0.x=oacc[nf][0]*inv0; o0.y=oacc[nf][1]*inv0;
    *(float2*)(Ob + (size_t)(m0+qr)*DIMM + nf*8+2*rr) = o0;
    float2 o1; o1.x=oacc[nf][2]*inv1; o1.y=oacc[nf][3]*inv1;
    *(float2*)(Ob + (size_t)(m0+qr+8)*DIMM + nf*8+2*rr) = o1;
  }
}

// ---------------- driver ----------------
extern "C" void kernel_launch(void* const* d_in, const int* in_sizes, int n_in,
                              void* d_out, int out_size){
  const float* x     =(const float*)d_in[0];
  const float* rpb   =(const float*)d_in[1];
  const float* ln1_g =(const float*)d_in[2];
  const float* ln1_b =(const float*)d_in[3];
  const float* w_qkv =(const float*)d_in[4];
  const float* w_out =(const float*)d_in[5];
  const float* b_out =(const float*)d_in[6];
  const float* ln2_g =(const float*)d_in[7];
  const float* ln2_b =(const float*)d_in[8];
  const float* w1    =(const float*)d_in[9];
  const float* b1    =(const float*)d_in[10];
  const float* w2    =(const float*)d_in[11];
  const float* b2    =(const float*)d_in[12];
  float* X = (float*)d_out;

  float *h, *qkv, *o, *ff;
  cudaGetSymbolAddress((void**)&h,   g_h);
  cudaGetSymbolAddress((void**)&qkv, g_qkv);
  cudaGetSymbolAddress((void**)&o,   g_o);
  cudaGetSymbolAddress((void**)&ff,  g_ffn);

  cudaFuncSetAttribute(attn_flash, cudaFuncAttributeMaxDynamicSharedMemorySize, FA_SMEM);

  copy_kernel<<<(NTOK*DIMM+255)/256, 256>>>(x, X, NTOK*DIMM);

  for(int l=0;l<NDEPTH;l++){
    // ---- attention block ----
    layernorm_kernel<<<NTOK,256>>>(X, ln1_g + l*DIMM, ln1_b + l*DIMM, h);
    gemm_tf32<0><<<dim3(24,16),256>>>(
        h, DIMM, w_qkv + (size_t)l*DIMM*3*DIMM, 3*DIMM,
        qkv, 3*DIMM, nullptr, nullptr, NTOK, 3*DIMM, DIMM);
    attn_flash<<<dim3(16,NBATCH*NHEADS),128,FA_SMEM>>>(qkv, rpb, o);
    gemm_tf32<1><<<dim3(8,16),256>>>(
        o, DIMM, w_out + (size_t)l*DIMM*DIMM, DIMM,
        X, DIMM, b_out + l*DIMM, X, NTOK, DIMM, DIMM);
    // ---- FFN block ----
    layernorm_kernel<<<NTOK,256>>>(X, ln2_g + l*DIMM, ln2_b + l*DIMM, h);
    gemm_tf32<2><<<dim3(32,16),256>>>(
        h, DIMM, w1 + (size_t)l*DIMM*FFD, FFD,
        ff, FFD, b1 + l*FFD, nullptr, NTOK, FFD, DIMM);
    gemm_tf32<1><<<dim3(8,16),256>>>(
        ff, FFD, w2 + (size_t)l*FFD*DIMM, DIMM,
        X, DIMM, b2 + l*DIMM, X, NTOK, DIMM, FFD);
  }
}

// round 5
// speedup vs baseline: 4.4007x; 1.3217x over previous
#include <cuda_runtime.h>
#include <cuda_fp16.h>
#include <math.h>
#include <stdint.h>

#define SEQ    1024
#define DIMM   1024
#define NHEADS 16
#define FFD    4096
#define NBATCH 2
#define NTOK   (NBATCH*SEQ)
#define NDEPTH 6

// ---------------- scratch (allocation-free: __device__ globals) ----------------
__device__ float g_h[NTOK*DIMM];                              //   8 MB
__device__ float g_qkv[NTOK*3*DIMM];                          //  24 MB
__device__ float g_o[NTOK*DIMM];                              //   8 MB
__device__ float g_ffn[NTOK*FFD];                             //  32 MB

// ---------------- helpers ----------------
__device__ __forceinline__ float to_tf32(float x){
  asm("cvt.rna.tf32.f32 %0, %0;" : "+f"(x));
  return x;
}
__device__ __forceinline__ uint32_t smem_u32(const void* p){
  uint32_t a;
  asm("{ .reg .u64 t; cvta.to.shared.u64 t, %1; cvt.u32.u64 %0, t; }" : "=r"(a) : "l"(p));
  return a;
}

__device__ __forceinline__ void mma8(float* d, const float* a, const float* b){
  asm volatile("mma.sync.aligned.m16n8k8.row.col.f32.tf32.tf32.f32 "
    "{%0,%1,%2,%3}, {%4,%5,%6,%7}, {%8,%9}, {%0,%1,%2,%3};\n"
    : "+f"(d[0]),"+f"(d[1]),"+f"(d[2]),"+f"(d[3])
    : "r"(__float_as_uint(a[0])),"r"(__float_as_uint(a[1])),
      "r"(__float_as_uint(a[2])),"r"(__float_as_uint(a[3])),
      "r"(__float_as_uint(b[0])),"r"(__float_as_uint(b[1])));
}

__device__ __forceinline__ void mma16h(float* d, const uint32_t* a, const uint32_t* b){
  asm volatile("mma.sync.aligned.m16n8k16.row.col.f32.f16.f16.f32 "
    "{%0,%1,%2,%3}, {%4,%5,%6,%7}, {%8,%9}, {%0,%1,%2,%3};\n"
    : "+f"(d[0]),"+f"(d[1]),"+f"(d[2]),"+f"(d[3])
    : "r"(a[0]),"r"(a[1]),"r"(a[2]),"r"(a[3]),
      "r"(b[0]),"r"(b[1]));
}

__device__ __forceinline__ void ldm_x4(uint32_t* r, uint32_t addr){
  asm volatile("ldmatrix.sync.aligned.m8n8.x4.shared.b16 {%0,%1,%2,%3}, [%4];"
    : "=r"(r[0]),"=r"(r[1]),"=r"(r[2]),"=r"(r[3]) : "r"(addr));
}
__device__ __forceinline__ void ldm_x4t(uint32_t* r, uint32_t addr){
  asm volatile("ldmatrix.sync.aligned.m8n8.x4.trans.shared.b16 {%0,%1,%2,%3}, [%4];"
    : "=r"(r[0]),"=r"(r[1]),"=r"(r[2]),"=r"(r[3]) : "r"(addr));
}

// ---------------- block reductions (blockDim.x == 256) ----------------
__device__ __forceinline__ float blockReduceSum(float val, float* sh){
  #pragma unroll
  for(int o=16;o>0;o>>=1) val += __shfl_xor_sync(0xffffffffu, val, o);
  int wid = threadIdx.x>>5;
  __syncthreads();
  if((threadIdx.x&31)==0) sh[wid]=val;
  __syncthreads();
  float r = 0.f;
  #pragma unroll
  for(int w=0;w<8;w++) r += sh[w];
  return r;
}

// ---------------- small kernels ----------------
__global__ void copy_kernel(const float* __restrict__ src, float* __restrict__ dst, int n){
  int i = blockIdx.x*blockDim.x + threadIdx.x;
  if(i<n) dst[i]=src[i];
}

__global__ void layernorm_kernel(const float* __restrict__ x, const float* __restrict__ g,
                                 const float* __restrict__ beta, float* __restrict__ out){
  __shared__ float sh[8];
  int row = blockIdx.x, t = threadIdx.x;
  const float4* xr = (const float4*)(x + (size_t)row*DIMM);
  float4 v = xr[t];
  float s = v.x+v.y+v.z+v.w;
  s = blockReduceSum(s, sh);
  float mu = s * (1.f/DIMM);
  float dx=v.x-mu, dy=v.y-mu, dz=v.z-mu, dw=v.w-mu;
  float ss = dx*dx+dy*dy+dz*dz+dw*dw;
  ss = blockReduceSum(ss, sh);
  float rinv = rsqrtf(ss*(1.f/DIMM) + 1e-5f);
  const float4 gg = ((const float4*)g)[t];
  const float4 bb = ((const float4*)beta)[t];
  float4 o;
  o.x = dx*rinv*gg.x + bb.x;
  o.y = dy*rinv*gg.y + bb.y;
  o.z = dz*rinv*gg.z + bb.z;
  o.w = dw*rinv*gg.w + bb.w;
  ((float4*)(out + (size_t)row*DIMM))[t] = o;
}

// ---------------- fp16 tensor-core GEMM (dense) ----------------
// C[M,N] = A[M,K] @ B[K,N] (+ epilogue). fp16 inputs (10-bit mantissa == tf32),
// fp32 accumulate. EPI: 0=none, 1=+bias+res, 2=gelu(+bias)
// 128x128x32 tile, 8 warps (2x4), warp tile 64x32, m16n8k16 via ldmatrix.
#define APITCH 40   // halves per A row (80B -> ldmatrix conflict-free)
#define BPITCH 136  // halves per B row (272B -> ldmatrix conflict-free)

template<int EPI>
__global__ void __launch_bounds__(256)
gemm_fp16(const float* __restrict__ A, int lda,
          const float* __restrict__ B, int ldb,
          float* __restrict__ C, int ldc,
          const float* __restrict__ bias, const float* __restrict__ res,
          int M, int N, int K)
{
  constexpr int BM=128, BN=128, BK=32;
  constexpr int MT=4, NT=4;
  __shared__ __half As[BM*APITCH];
  __shared__ __half Bs[BK*BPITCH];

  int t=threadIdx.x;
  const float* Ag = A + (size_t)blockIdx.y*BM*lda;
  const float* Bg = B + blockIdx.x*BN;

  float4 pa[4]; float4 pb[4];
  #pragma unroll
  for(int i=0;i<4;i++){
    int idx=t+256*i;
    pa[i]=*(const float4*)(Ag + (size_t)(idx>>3)*lda + ((idx&7)<<2));
  }
  #pragma unroll
  for(int i=0;i<4;i++){
    int idx=t+256*i;
    pb[i]=*(const float4*)(Bg + (size_t)(idx>>5)*ldb + ((idx&31)<<2));
  }

  float acc[MT][NT][4];
  #pragma unroll
  for(int i=0;i<MT;i++)
    #pragma unroll
    for(int j=0;j<NT;j++)
      #pragma unroll
      for(int r=0;r<4;r++) acc[i][j][r]=0.f;

  int wid=t>>5, lane=t&31;
  int wm=wid>>2, wn=wid&3;
  int m0=wm*64, n0=wn*32;
  int qr=lane>>2, rr=lane&3;

  uint32_t sA = smem_u32(As), sB = smem_u32(Bs);
  // ldmatrix lane-address bases
  uint32_t a_base = sA + (uint32_t)(((m0 + (lane&15))*APITCH + (lane>>4)*8) * 2);
  uint32_t b_base = sB + (uint32_t)(((lane&15))*BPITCH + n0 + (lane>>4)*8) * 2;

  for(int k0=0;k0<K;k0+=BK){
    __syncthreads();
    #pragma unroll
    for(int i=0;i<4;i++){
      int idx=t+256*i; int m=idx>>3, c=(idx&7)<<2;
      __half2 h01 = __floats2half2_rn(pa[i].x, pa[i].y);
      __half2 h23 = __floats2half2_rn(pa[i].z, pa[i].w);
      uint2 u; u.x = *(uint32_t*)&h01; u.y = *(uint32_t*)&h23;
      *(uint2*)(As + m*APITCH + c) = u;
    }
    #pragma unroll
    for(int i=0;i<4;i++){
      int idx=t+256*i; int kk=idx>>5, cc=(idx&31)<<2;
      __half2 h01 = __floats2half2_rn(pb[i].x, pb[i].y);
      __half2 h23 = __floats2half2_rn(pb[i].z, pb[i].w);
      uint2 u; u.x = *(uint32_t*)&h01; u.y = *(uint32_t*)&h23;
      *(uint2*)(Bs + kk*BPITCH + cc) = u;
    }
    __syncthreads();
    if(k0+BK<K){
      const float* Ag2 = Ag + k0 + BK;
      #pragma unroll
      for(int i=0;i<4;i++){
        int idx=t+256*i;
        pa[i]=*(const float4*)(Ag2 + (size_t)(idx>>3)*lda + ((idx&7)<<2));
      }
      const float* Bg2 = Bg + (size_t)(k0+BK)*ldb;
      #pragma unroll
      for(int i=0;i<4;i++){
        int idx=t+256*i;
        pb[i]=*(const float4*)(Bg2 + (size_t)(idx>>5)*ldb + ((idx&31)<<2));
      }
    }
    #pragma unroll
    for(int ks=0;ks<2;ks++){
      uint32_t af[MT][4];
      #pragma unroll
      for(int mt=0;mt<MT;mt++)
        ldm_x4(af[mt], a_base + (uint32_t)((mt*16*APITCH + ks*16)*2));
      uint32_t bf[2][4];
      #pragma unroll
      for(int nh=0;nh<2;nh++)
        ldm_x4t(bf[nh], b_base + (uint32_t)((ks*16*BPITCH + nh*16)*2));
      #pragma unroll
      for(int mt=0;mt<MT;mt++)
        #pragma unroll
        for(int nt=0;nt<NT;nt++)
          mma16h(acc[mt][nt], af[mt], &bf[nt>>1][(nt&1)*2]);
    }
  }

  int brow = blockIdx.y*BM + m0 + qr;
  int bcol = blockIdx.x*BN + n0 + (rr<<1);
  #pragma unroll
  for(int mt=0;mt<MT;mt++){
    #pragma unroll
    for(int nt=0;nt<NT;nt++){
      int col = bcol + nt*8;
      #pragma unroll
      for(int hh=0;hh<2;hh++){
        int row = brow + mt*16 + hh*8;
        float vx = acc[mt][nt][2*hh+0];
        float vy = acc[mt][nt][2*hh+1];
        if(EPI==1||EPI==2){ vx += bias[col]; vy += bias[col+1]; }
        if(EPI==2){
          vx = 0.5f*vx*(1.f+erff(vx*0.70710678118654752f));
          vy = 0.5f*vy*(1.f+erff(vy*0.70710678118654752f));
        }
        if(EPI==1){
          vx += res[(size_t)row*ldc+col];
          vy += res[(size_t)row*ldc+col+1];
        }
        float2 o; o.x=vx; o.y=vy;
        *(float2*)(C + (size_t)row*ldc + col) = o;
      }
    }
  }
}

// ---------------- fused flash attention (unchanged from R4) ----------------
#define PAD_P 68
#define PAD_K 68
#define PAD_V 72
#define FA_SMEM ((64*PAD_P + 64*PAD_K + 64*PAD_V)*4)

__global__ void __launch_bounds__(128)
attn_flash(const float* __restrict__ qkv, const float* __restrict__ rpb,
           float* __restrict__ O)
{
  extern __shared__ float fsm[];
  float* Ps = fsm;
  float* Ks = fsm + 64*PAD_P;
  float* Vs = fsm + 64*(PAD_P+PAD_K);

  int t = threadIdx.x, lane = t&31, w = t>>5;
  int qr = lane>>2, rr = lane&3;
  int it = blockIdx.x, bh = blockIdx.y;
  int b = bh>>4, h = bh&15;
  const float* Qg = qkv + (size_t)(b*SEQ + it*64)*(3*DIMM) + h*64;
  const float* Kg = qkv + (size_t)b*SEQ*(3*DIMM) + DIMM   + h*64;
  const float* Vg = qkv + (size_t)b*SEQ*(3*DIMM) + 2*DIMM + h*64;
  const float* Rg = rpb + ((size_t)h*SEQ + it*64)*SEQ;

  #pragma unroll
  for(int u=0;u<8;u++){
    int idx = t + 128*u;
    int r = idx>>4, c = (idx&15)<<2;
    float4 v = *(const float4*)(Qg + (size_t)r*(3*DIMM) + c);
    v.x=to_tf32(v.x); v.y=to_tf32(v.y); v.z=to_tf32(v.z); v.w=to_tf32(v.w);
    *(float4*)(Ps + r*PAD_P + c) = v;
  }
  __syncthreads();
  int m0 = w*16;
  float qf[8][4];
  #pragma unroll
  for(int kk=0;kk<8;kk++){
    qf[kk][0]=Ps[(m0+qr  )*PAD_P + kk*8+rr];
    qf[kk][1]=Ps[(m0+qr+8)*PAD_P + kk*8+rr];
    qf[kk][2]=Ps[(m0+qr  )*PAD_P + kk*8+rr+4];
    qf[kk][3]=Ps[(m0+qr+8)*PAD_P + kk*8+rr+4];
  }
  __syncthreads();

  float oacc[8][4];
  #pragma unroll
  for(int nf=0;nf<8;nf++)
    #pragma unroll
    for(int r=0;r<4;r++) oacc[nf][r]=0.f;
  float mrow0=-1e30f, mrow1=-1e30f, lrow0=0.f, lrow1=0.f;

  for(int j0=0;j0<SEQ;j0+=64){
    #pragma unroll
    for(int u=0;u<8;u++){
      int idx = t + 128*u;
      int r = idx>>4, c = (idx&15)<<2;
      float4 kv = *(const float4*)(Kg + (size_t)(j0+r)*(3*DIMM) + c);
      kv.x=to_tf32(kv.x); kv.y=to_tf32(kv.y); kv.z=to_tf32(kv.z); kv.w=to_tf32(kv.w);
      *(float4*)(Ks + r*PAD_K + c) = kv;
      float4 vv = *(const float4*)(Vg + (size_t)(j0+r)*(3*DIMM) + c);
      vv.x=to_tf32(vv.x); vv.y=to_tf32(vv.y); vv.z=to_tf32(vv.z); vv.w=to_tf32(vv.w);
      *(float4*)(Vs + r*PAD_V + c) = vv;
    }
    __syncthreads();

    float s[8][4];
    #pragma unroll
    for(int nf=0;nf<8;nf++)
      #pragma unroll
      for(int r=0;r<4;r++) s[nf][r]=0.f;
    #pragma unroll
    for(int kk=0;kk<8;kk++){
      float bf[8][2];
      #pragma unroll
      for(int nf=0;nf<8;nf++){
        bf[nf][0]=Ks[(nf*8+qr)*PAD_K + kk*8+rr];
        bf[nf][1]=Ks[(nf*8+qr)*PAD_K + kk*8+rr+4];
      }
      #pragma unroll
      for(int nf=0;nf<8;nf++) mma8(s[nf], qf[kk], bf[nf]);
    }
    #pragma unroll
    for(int nf=0;nf<8;nf++){
      const float* rp = Rg + (size_t)(m0+qr)*SEQ + j0 + nf*8 + 2*rr;
      float2 r0 = *(const float2*)rp;
      float2 r1 = *(const float2*)(rp + 8*SEQ);
      s[nf][0]=fmaf(s[nf][0],0.125f,r0.x);
      s[nf][1]=fmaf(s[nf][1],0.125f,r0.y);
      s[nf][2]=fmaf(s[nf][2],0.125f,r1.x);
      s[nf][3]=fmaf(s[nf][3],0.125f,r1.y);
    }
    float mx0=-1e30f, mx1=-1e30f;
    #pragma unroll
    for(int nf=0;nf<8;nf++){
      mx0=fmaxf(mx0,fmaxf(s[nf][0],s[nf][1]));
      mx1=fmaxf(mx1,fmaxf(s[nf][2],s[nf][3]));
    }
    mx0=fmaxf(mx0,__shfl_xor_sync(0xffffffffu,mx0,1));
    mx0=fmaxf(mx0,__shfl_xor_sync(0xffffffffu,mx0,2));
    mx1=fmaxf(mx1,__shfl_xor_sync(0xffffffffu,mx1,1));
    mx1=fmaxf(mx1,__shfl_xor_sync(0xffffffffu,mx1,2));
    float mn0=fmaxf(mrow0,mx0), mn1=fmaxf(mrow1,mx1);
    float a0=__expf(mrow0-mn0), a1=__expf(mrow1-mn1);
    mrow0=mn0; mrow1=mn1;
    float sum0=0.f, sum1=0.f;
    #pragma unroll
    for(int nf=0;nf<8;nf++){
      s[nf][0]=__expf(s[nf][0]-mn0); s[nf][1]=__expf(s[nf][1]-mn0);
      s[nf][2]=__expf(s[nf][2]-mn1); s[nf][3]=__expf(s[nf][3]-mn1);
      sum0 += s[nf][0]+s[nf][1];
      sum1 += s[nf][2]+s[nf][3];
    }
    sum0 += __shfl_xor_sync(0xffffffffu,sum0,1);
    sum0 += __shfl_xor_sync(0xffffffffu,sum0,2);
    sum1 += __shfl_xor_sync(0xffffffffu,sum1,1);
    sum1 += __shfl_xor_sync(0xffffffffu,sum1,2);
    lrow0 = lrow0*a0 + sum0;
    lrow1 = lrow1*a1 + sum1;
    #pragma unroll
    for(int nf=0;nf<8;nf++){
      oacc[nf][0]*=a0; oacc[nf][1]*=a0;
      oacc[nf][2]*=a1; oacc[nf][3]*=a1;
    }
    #pragma unroll
    for(int nf=0;nf<8;nf++){
      Ps[(m0+qr  )*PAD_P + nf*8+2*rr  ]=to_tf32(s[nf][0]);
      Ps[(m0+qr  )*PAD_P + nf*8+2*rr+1]=to_tf32(s[nf][1]);
      Ps[(m0+qr+8)*PAD_P + nf*8+2*rr  ]=to_tf32(s[nf][2]);
      Ps[(m0+qr+8)*PAD_P + nf*8+2*rr+1]=to_tf32(s[nf][3]);
    }
    __syncwarp();
    #pragma unroll
    for(int kk=0;kk<8;kk++){
      float af[4];
      af[0]=Ps[(m0+qr  )*PAD_P + kk*8+rr];
      af[1]=Ps[(m0+qr+8)*PAD_P + kk*8+rr];
      af[2]=Ps[(m0+qr  )*PAD_P + kk*8+rr+4];
      af[3]=Ps[(m0+qr+8)*PAD_P + kk*8+rr+4];
      #pragma unroll
      for(int nf=0;nf<8;nf++){
        float bf2[2];
        bf2[0]=Vs[(kk*8+rr  )*PAD_V + nf*8+qr];
        bf2[1]=Vs[(kk*8+rr+4)*PAD_V + nf*8+qr];
        mma8(oacc[nf], af, bf2);
      }
    }
    __syncthreads();
  }

  float inv0=1.f/lrow0, inv1=1.f/lrow1;
  float* Ob = O + (size_t)(b*SEQ + it*64)*DIMM + h*64;
  #pragma unroll
  for(int nf=0;nf<8;nf++){
    float2 o0; o0.x=oacc[nf][0]*inv0; o0.y=oacc[nf][1]*inv0;
    *(float2*)(Ob + (size_t)(m0+qr)*DIMM + nf*8+2*rr) = o0;
    float2 o1; o1.x=oacc[nf][2]*inv1; o1.y=oacc[nf][3]*inv1;
    *(float2*)(Ob + (size_t)(m0+qr+8)*DIMM + nf*8+2*rr) = o1;
  }
}

// ---------------- driver ----------------
extern "C" void kernel_launch(void* const* d_in, const int* in_sizes, int n_in,
                              void* d_out, int out_size){
  const float* x     =(const float*)d_in[0];
  const float* rpb   =(const float*)d_in[1];
  const float* ln1_g =(const float*)d_in[2];
  const float* ln1_b =(const float*)d_in[3];
  const float* w_qkv =(const float*)d_in[4];
  const float* w_out =(const float*)d_in[5];
  const float* b_out =(const float*)d_in[6];
  const float* ln2_g =(const float*)d_in[7];
  const float* ln2_b =(const float*)d_in[8];
  const float* w1    =(const float*)d_in[9];
  const float* b1    =(const float*)d_in[10];
  const float* w2    =(const float*)d_in[11];
  const float* b2    =(const float*)d_in[12];
  float* X = (float*)d_out;

  float *h, *qkv, *o, *ff;
  cudaGetSymbolAddress((void**)&h,   g_h);
  cudaGetSymbolAddress((void**)&qkv, g_qkv);
  cudaGetSymbolAddress((void**)&o,   g_o);
  cudaGetSymbolAddress((void**)&ff,  g_ffn);

  cudaFuncSetAttribute(attn_flash, cudaFuncAttributeMaxDynamicSharedMemorySize, FA_SMEM);

  copy_kernel<<<(NTOK*DIMM+255)/256, 256>>>(x, X, NTOK*DIMM);

  for(int l=0;l<NDEPTH;l++){
    // ---- attention block ----
    layernorm_kernel<<<NTOK,256>>>(X, ln1_g + l*DIMM, ln1_b + l*DIMM, h);
    gemm_fp16<0><<<dim3(24,16),256>>>(
        h, DIMM, w_qkv + (size_t)l*DIMM*3*DIMM, 3*DIMM,
        qkv, 3*DIMM, nullptr, nullptr, NTOK, 3*DIMM, DIMM);
    attn_flash<<<dim3(16,NBATCH*NHEADS),128,FA_SMEM>>>(qkv, rpb, o);
    gemm_fp16<1><<<dim3(8,16),256>>>(
        o, DIMM, w_out + (size_t)l*DIMM*DIMM, DIMM,
        X, DIMM, b_out + l*DIMM, X, NTOK, DIMM, DIMM);
    // ---- FFN block ----
    layernorm_kernel<<<NTOK,256>>>(X, ln2_g + l*DIMM, ln2_b + l*DIMM, h);
    gemm_fp16<2><<<dim3(32,16),256>>>(
        h, DIMM, w1 + (size_t)l*DIMM*FFD, FFD,
        ff, FFD, b1 + l*FFD, nullptr, NTOK, FFD, DIMM);
    gemm_fp16<1><<<dim3(8,16),256>>>(
        ff, FFD, w2 + (size_t)l*FFD*DIMM, DIMM,
        X, DIMM, b2 + l*DIMM, X, NTOK, DIMM, FFD);
  }
}

// round 6
// speedup vs baseline: 6.3055x; 1.4328x over previous
#include <cuda_runtime.h>
#include <cuda_fp16.h>
#include <math.h>
#include <stdint.h>

#define SEQ    1024
#define DIMM   1024
#define NHEADS 16
#define FFD    4096
#define NBATCH 2
#define NTOK   (NBATCH*SEQ)
#define NDEPTH 6

// ---------------- scratch (allocation-free: __device__ globals) ----------------
__device__ __half g_hh[NTOK*DIMM];                 // LN output, fp16
__device__ __half g_qkvh[NTOK*3*DIMM];             // qkv, fp16
__device__ __half g_oh[NTOK*DIMM];                 // attention out, fp16
__device__ __half g_ffh[NTOK*FFD];                 // FFN mid, fp16
__device__ __half g_wqkvh[(size_t)NDEPTH*DIMM*3*DIMM];
__device__ __half g_wouth[(size_t)NDEPTH*DIMM*DIMM];
__device__ __half g_w1h[(size_t)NDEPTH*DIMM*FFD];
__device__ __half g_w2h[(size_t)NDEPTH*FFD*DIMM];

// ---------------- ptx helpers ----------------
__device__ __forceinline__ uint32_t smem_u32(const void* p){
  uint32_t a;
  asm("{ .reg .u64 t; cvta.to.shared.u64 t, %1; cvt.u32.u64 %0, t; }" : "=r"(a) : "l"(p));
  return a;
}
__device__ __forceinline__ void mma16h(float* d, const uint32_t* a, const uint32_t* b){
  asm volatile("mma.sync.aligned.m16n8k16.row.col.f32.f16.f16.f32 "
    "{%0,%1,%2,%3}, {%4,%5,%6,%7}, {%8,%9}, {%0,%1,%2,%3};\n"
    : "+f"(d[0]),"+f"(d[1]),"+f"(d[2]),"+f"(d[3])
    : "r"(a[0]),"r"(a[1]),"r"(a[2]),"r"(a[3]),
      "r"(b[0]),"r"(b[1]));
}
__device__ __forceinline__ void ldm_x4(uint32_t* r, uint32_t addr){
  asm volatile("ldmatrix.sync.aligned.m8n8.x4.shared.b16 {%0,%1,%2,%3}, [%4];"
    : "=r"(r[0]),"=r"(r[1]),"=r"(r[2]),"=r"(r[3]) : "r"(addr));
}
__device__ __forceinline__ void ldm_x4t(uint32_t* r, uint32_t addr){
  asm volatile("ldmatrix.sync.aligned.m8n8.x4.trans.shared.b16 {%0,%1,%2,%3}, [%4];"
    : "=r"(r[0]),"=r"(r[1]),"=r"(r[2]),"=r"(r[3]) : "r"(addr));
}
__device__ __forceinline__ void cp16(uint32_t smem, const void* g){
  asm volatile("cp.async.cg.shared.global [%0], [%1], 16;" :: "r"(smem), "l"(g));
}
#define CP_COMMIT() asm volatile("cp.async.commit_group;" ::: "memory")
#define CP_WAIT0()  asm volatile("cp.async.wait_group 0;" ::: "memory")
#define CP_WAIT1()  asm volatile("cp.async.wait_group 1;" ::: "memory")

__device__ __forceinline__ uint32_t packh2(float x, float y){
  __half2 h = __floats2half2_rn(x, y);
  return *(uint32_t*)&h;
}

// ---------------- block reductions (blockDim.x == 256) ----------------
__device__ __forceinline__ float blockReduceSum(float val, float* sh){
  #pragma unroll
  for(int o=16;o>0;o>>=1) val += __shfl_xor_sync(0xffffffffu, val, o);
  int wid = threadIdx.x>>5;
  __syncthreads();
  if((threadIdx.x&31)==0) sh[wid]=val;
  __syncthreads();
  float r = 0.f;
  #pragma unroll
  for(int w=0;w<8;w++) r += sh[w];
  return r;
}

// ---------------- small kernels ----------------
__global__ void copy_kernel(const float* __restrict__ src, float* __restrict__ dst, int n){
  int i = blockIdx.x*blockDim.x + threadIdx.x;
  if(i<n) dst[i]=src[i];
}

__global__ void conv_half(const float* __restrict__ src, __half* __restrict__ dst, int n4){
  int i = blockIdx.x*blockDim.x + threadIdx.x;
  if(i<n4){
    float4 v = ((const float4*)src)[i];
    uint2 u;
    u.x = packh2(v.x, v.y);
    u.y = packh2(v.z, v.w);
    ((uint2*)dst)[i] = u;
  }
}

// LayerNorm: fp32 in, fp16 out
__global__ void layernorm_h(const float* __restrict__ x, const float* __restrict__ g,
                            const float* __restrict__ beta, __half* __restrict__ out){
  __shared__ float sh[8];
  int row = blockIdx.x, t = threadIdx.x;
  const float4* xr = (const float4*)(x + (size_t)row*DIMM);
  float4 v = xr[t];
  float s = v.x+v.y+v.z+v.w;
  s = blockReduceSum(s, sh);
  float mu = s * (1.f/DIMM);
  float dx=v.x-mu, dy=v.y-mu, dz=v.z-mu, dw=v.w-mu;
  float ss = dx*dx+dy*dy+dz*dz+dw*dw;
  ss = blockReduceSum(ss, sh);
  float rinv = rsqrtf(ss*(1.f/DIMM) + 1e-5f);
  const float4 gg = ((const float4*)g)[t];
  const float4 bb = ((const float4*)beta)[t];
  uint2 u;
  u.x = packh2(dx*rinv*gg.x + bb.x, dy*rinv*gg.y + bb.y);
  u.y = packh2(dz*rinv*gg.z + bb.z, dw*rinv*gg.w + bb.w);
  ((uint2*)(out + (size_t)row*DIMM))[t] = u;
}

// ---------------- fp16 tensor-core GEMM (dense, fp16 in / OT out) ----------------
// EPI: 0=none(half out), 1=+bias+res(float out), 2=gelu(+bias)(half out)
#define APITCH 40
#define BPITCH 136

template<int EPI, typename OT>
__global__ void __launch_bounds__(256)
gemm_h(const __half* __restrict__ A, int lda,
       const __half* __restrict__ B, int ldb,
       OT* __restrict__ C, int ldc,
       const float* __restrict__ bias, const float* __restrict__ res,
       int M, int N, int K)
{
  constexpr int BM=128, BN=128, BK=32;
  constexpr int MT=4, NT=4;
  __shared__ __half As[BM*APITCH];
  __shared__ __half Bs[BK*BPITCH];

  int t=threadIdx.x;
  const __half* Ag = A + (size_t)blockIdx.y*BM*lda;
  const __half* Bg = B + blockIdx.x*BN;

  uint4 pa[2]; uint4 pb[2];
  #pragma unroll
  for(int i=0;i<2;i++){
    int c=t+256*i;
    pa[i]=*(const uint4*)(Ag + (size_t)(c>>2)*lda + ((c&3)<<3));
  }
  #pragma unroll
  for(int i=0;i<2;i++){
    int c=t+256*i;
    pb[i]=*(const uint4*)(Bg + (size_t)(c>>4)*ldb + ((c&15)<<3));
  }

  float acc[MT][NT][4];
  #pragma unroll
  for(int i=0;i<MT;i++)
    #pragma unroll
    for(int j=0;j<NT;j++)
      #pragma unroll
      for(int r=0;r<4;r++) acc[i][j][r]=0.f;

  int wid=t>>5, lane=t&31;
  int wm=wid>>2, wn=wid&3;
  int m0=wm*64, n0=wn*32;
  int qr=lane>>2, rr=lane&3;

  uint32_t sA = smem_u32(As), sB = smem_u32(Bs);
  uint32_t a_base = sA + (uint32_t)(((m0 + (lane&15))*APITCH + (lane>>4)*8) * 2);
  uint32_t b_base = sB + (uint32_t)(((lane&15))*BPITCH + n0 + (lane>>4)*8) * 2;

  for(int k0=0;k0<K;k0+=BK){
    __syncthreads();
    #pragma unroll
    for(int i=0;i<2;i++){
      int c=t+256*i;
      *(uint4*)(As + (c>>2)*APITCH + ((c&3)<<3)) = pa[i];
    }
    #pragma unroll
    for(int i=0;i<2;i++){
      int c=t+256*i;
      *(uint4*)(Bs + (c>>4)*BPITCH + ((c&15)<<3)) = pb[i];
    }
    __syncthreads();
    if(k0+BK<K){
      const __half* Ag2 = Ag + k0 + BK;
      #pragma unroll
      for(int i=0;i<2;i++){
        int c=t+256*i;
        pa[i]=*(const uint4*)(Ag2 + (size_t)(c>>2)*lda + ((c&3)<<3));
      }
      const __half* Bg2 = Bg + (size_t)(k0+BK)*ldb;
      #pragma unroll
      for(int i=0;i<2;i++){
        int c=t+256*i;
        pb[i]=*(const uint4*)(Bg2 + (size_t)(c>>4)*ldb + ((c&15)<<3));
      }
    }
    #pragma unroll
    for(int ks=0;ks<2;ks++){
      uint32_t af[MT][4];
      #pragma unroll
      for(int mt=0;mt<MT;mt++)
        ldm_x4(af[mt], a_base + (uint32_t)((mt*16*APITCH + ks*16)*2));
      uint32_t bf[2][4];
      #pragma unroll
      for(int nh=0;nh<2;nh++)
        ldm_x4t(bf[nh], b_base + (uint32_t)((ks*16*BPITCH + nh*16)*2));
      #pragma unroll
      for(int mt=0;mt<MT;mt++)
        #pragma unroll
        for(int nt=0;nt<NT;nt++)
          mma16h(acc[mt][nt], af[mt], &bf[nt>>1][(nt&1)*2]);
    }
  }

  int brow = blockIdx.y*BM + m0 + qr;
  int bcol = blockIdx.x*BN + n0 + (rr<<1);
  #pragma unroll
  for(int mt=0;mt<MT;mt++){
    #pragma unroll
    for(int nt=0;nt<NT;nt++){
      int col = bcol + nt*8;
      #pragma unroll
      for(int hh=0;hh<2;hh++){
        int row = brow + mt*16 + hh*8;
        float vx = acc[mt][nt][2*hh+0];
        float vy = acc[mt][nt][2*hh+1];
        if(EPI==1||EPI==2){ vx += bias[col]; vy += bias[col+1]; }
        if(EPI==2){
          vx = 0.5f*vx*(1.f+erff(vx*0.70710678118654752f));
          vy = 0.5f*vy*(1.f+erff(vy*0.70710678118654752f));
        }
        if(EPI==1){
          vx += res[(size_t)row*ldc+col];
          vy += res[(size_t)row*ldc+col+1];
        }
        if(sizeof(OT)==2){
          *(uint32_t*)((__half*)C + (size_t)row*ldc + col) = packh2(vx,vy);
        }else{
          float2 o; o.x=vx; o.y=vy;
          *(float2*)((float*)C + (size_t)row*ldc + col) = o;
        }
      }
    }
  }
}

// ---------------- fused flash attention, fp16 mma + cp.async ----------------
// grid (16 i-tiles, 32 bh), 128 threads (4 warps), 64-row Q tile.
#define FPITCH 72

__global__ void __launch_bounds__(128)
attn_flash_h(const __half* __restrict__ qkv, const float* __restrict__ rpb,
             __half* __restrict__ O)
{
  __shared__ __half Qs[64*FPITCH];
  __shared__ __half Ks[2*64*FPITCH];
  __shared__ __half Vs[2*64*FPITCH];

  int t = threadIdx.x, lane = t&31, w = t>>5;
  int qr = lane>>2, rr = lane&3;
  int it = blockIdx.x, bh = blockIdx.y;
  int b = bh>>4, h = bh&15;
  const __half* Qg = qkv + (size_t)(b*SEQ + it*64)*(3*DIMM) + h*64;
  const __half* Kg = qkv + (size_t)b*SEQ*(3*DIMM) + DIMM   + h*64;
  const __half* Vg = qkv + (size_t)b*SEQ*(3*DIMM) + 2*DIMM + h*64;
  const float* Rg = rpb + ((size_t)h*SEQ + it*64)*SEQ;

  uint32_t sQ = smem_u32(Qs), sK = smem_u32(Ks), sV = smem_u32(Vs);

  // prologue: Q + KV tile0 (group0), KV tile1 (group1)
  #pragma unroll
  for(int u=0;u<4;u++){
    int c = t + 128*u;            // 0..511
    int row = c>>3, cc = c&7;
    cp16(sQ + (uint32_t)(row*FPITCH + cc*8)*2, Qg + (size_t)row*(3*DIMM) + cc*8);
  }
  #pragma unroll
  for(int u=0;u<8;u++){
    int c = t + 128*u;            // 0..1023
    int mat = c>>9, row=(c>>3)&63, cc=c&7;
    const __half* src = (mat? Vg:Kg) + (size_t)row*(3*DIMM) + cc*8;
    uint32_t dst = (mat? sV:sK) + (uint32_t)(row*FPITCH + cc*8)*2;
    cp16(dst, src);
  }
  CP_COMMIT();
  #pragma unroll
  for(int u=0;u<8;u++){
    int c = t + 128*u;
    int mat = c>>9, row=(c>>3)&63, cc=c&7;
    const __half* src = (mat? Vg:Kg) + (size_t)(64+row)*(3*DIMM) + cc*8;
    uint32_t dst = (mat? sV:sK) + (uint32_t)(64*FPITCH + row*FPITCH + cc*8)*2;
    cp16(dst, src);
  }
  CP_COMMIT();

  int m0 = w*16;
  // fragment base addresses
  uint32_t a_base  = sQ + (uint32_t)(((m0 + (lane&15))*FPITCH + (lane>>4)*8)*2);
  uint32_t k_lbase = (uint32_t)((((lane&7) + ((lane&16)?8:0))*FPITCH + ((lane&8)?8:0))*2);
  uint32_t v_lbase = (uint32_t)(((lane&15)*FPITCH + (lane>>4)*8)*2);

  uint32_t qf[4][4];
  float oacc[8][4];
  #pragma unroll
  for(int nf=0;nf<8;nf++)
    #pragma unroll
    for(int r=0;r<4;r++) oacc[nf][r]=0.f;
  float mrow0=-1e30f, mrow1=-1e30f, lrow0=0.f, lrow1=0.f;

  for(int jt=0;jt<16;jt++){
    if(jt<15) CP_WAIT1(); else CP_WAIT0();
    __syncthreads();
    if(jt==0){
      #pragma unroll
      for(int kb=0;kb<4;kb++) ldm_x4(qf[kb], a_base + (uint32_t)(kb*16*2));
    }
    uint32_t bufK = sK + (uint32_t)((jt&1)*64*FPITCH*2);
    uint32_t bufV = sV + (uint32_t)((jt&1)*64*FPITCH*2);

    // ---- S = Q K^T ----
    float s[8][4];
    #pragma unroll
    for(int nf=0;nf<8;nf++)
      #pragma unroll
      for(int r=0;r<4;r++) s[nf][r]=0.f;
    #pragma unroll
    for(int kb=0;kb<4;kb++){
      #pragma unroll
      for(int jnp=0;jnp<4;jnp++){
        uint32_t kr[4];
        ldm_x4(kr, bufK + k_lbase + (uint32_t)((jnp*16*FPITCH + kb*16)*2));
        mma16h(s[2*jnp  ], qf[kb], kr);
        mma16h(s[2*jnp+1], qf[kb], kr+2);
      }
    }
    // ---- scale + rpb ----
    #pragma unroll
    for(int nf=0;nf<8;nf++){
      const float* rp = Rg + (size_t)(m0+qr)*SEQ + jt*64 + nf*8 + 2*rr;
      float2 r0 = *(const float2*)rp;
      float2 r1 = *(const float2*)(rp + 8*SEQ);
      s[nf][0]=fmaf(s[nf][0],0.125f,r0.x);
      s[nf][1]=fmaf(s[nf][1],0.125f,r0.y);
      s[nf][2]=fmaf(s[nf][2],0.125f,r1.x);
      s[nf][3]=fmaf(s[nf][3],0.125f,r1.y);
    }
    // ---- online softmax ----
    float mx0=-1e30f, mx1=-1e30f;
    #pragma unroll
    for(int nf=0;nf<8;nf++){
      mx0=fmaxf(mx0,fmaxf(s[nf][0],s[nf][1]));
      mx1=fmaxf(mx1,fmaxf(s[nf][2],s[nf][3]));
    }
    mx0=fmaxf(mx0,__shfl_xor_sync(0xffffffffu,mx0,1));
    mx0=fmaxf(mx0,__shfl_xor_sync(0xffffffffu,mx0,2));
    mx1=fmaxf(mx1,__shfl_xor_sync(0xffffffffu,mx1,1));
    mx1=fmaxf(mx1,__shfl_xor_sync(0xffffffffu,mx1,2));
    float mn0=fmaxf(mrow0,mx0), mn1=fmaxf(mrow1,mx1);
    float a0=__expf(mrow0-mn0), a1=__expf(mrow1-mn1);
    mrow0=mn0; mrow1=mn1;
    float sum0=0.f, sum1=0.f;
    #pragma unroll
    for(int nf=0;nf<8;nf++){
      s[nf][0]=__expf(s[nf][0]-mn0); s[nf][1]=__expf(s[nf][1]-mn0);
      s[nf][2]=__expf(s[nf][2]-mn1); s[nf][3]=__expf(s[nf][3]-mn1);
      sum0 += s[nf][0]+s[nf][1];
      sum1 += s[nf][2]+s[nf][3];
    }
    sum0 += __shfl_xor_sync(0xffffffffu,sum0,1);
    sum0 += __shfl_xor_sync(0xffffffffu,sum0,2);
    sum1 += __shfl_xor_sync(0xffffffffu,sum1,1);
    sum1 += __shfl_xor_sync(0xffffffffu,sum1,2);
    lrow0 = lrow0*a0 + sum0;
    lrow1 = lrow1*a1 + sum1;
    #pragma unroll
    for(int nf=0;nf<8;nf++){
      oacc[nf][0]*=a0; oacc[nf][1]*=a0;
      oacc[nf][2]*=a1; oacc[nf][3]*=a1;
    }
    // ---- pack P fragments directly in registers (FA2 trick) ----
    uint32_t pf[4][4];
    #pragma unroll
    for(int kb=0;kb<4;kb++){
      pf[kb][0]=packh2(s[2*kb  ][0], s[2*kb  ][1]);
      pf[kb][1]=packh2(s[2*kb  ][2], s[2*kb  ][3]);
      pf[kb][2]=packh2(s[2*kb+1][0], s[2*kb+1][1]);
      pf[kb][3]=packh2(s[2*kb+1][2], s[2*kb+1][3]);
    }
    // ---- O += P V ----
    #pragma unroll
    for(int kb=0;kb<4;kb++){
      #pragma unroll
      for(int nfp=0;nfp<4;nfp++){
        uint32_t vr[4];
        ldm_x4t(vr, bufV + v_lbase + (uint32_t)((kb*16*FPITCH + nfp*16)*2));
        mma16h(oacc[2*nfp  ], pf[kb], vr);
        mma16h(oacc[2*nfp+1], pf[kb], vr+2);
      }
    }
    __syncthreads();
    if(jt<14){
      int nt = jt+2, buf = jt&1;
      #pragma unroll
      for(int u=0;u<8;u++){
        int c = t + 128*u;
        int mat = c>>9, row=(c>>3)&63, cc=c&7;
        const __half* src = (mat? Vg:Kg) + (size_t)(nt*64+row)*(3*DIMM) + cc*8;
        uint32_t dst = (mat? sV:sK) + (uint32_t)(buf*64*FPITCH + row*FPITCH + cc*8)*2;
        cp16(dst, src);
      }
      CP_COMMIT();
    }
  }

  // ---- epilogue: O/l, fp16 out ----
  float inv0=1.f/lrow0, inv1=1.f/lrow1;
  __half* Ob = O + (size_t)(b*SEQ + it*64)*DIMM + h*64;
  #pragma unroll
  for(int nf=0;nf<8;nf++){
    *(uint32_t*)(Ob + (size_t)(m0+qr  )*DIMM + nf*8+2*rr) = packh2(oacc[nf][0]*inv0, oacc[nf][1]*inv0);
    *(uint32_t*)(Ob + (size_t)(m0+qr+8)*DIMM + nf*8+2*rr) = packh2(oacc[nf][2]*inv1, oacc[nf][3]*inv1);
  }
}

// ---------------- driver ----------------
extern "C" void kernel_launch(void* const* d_in, const int* in_sizes, int n_in,
                              void* d_out, int out_size){
  const float* x     =(const float*)d_in[0];
  const float* rpb   =(const float*)d_in[1];
  const float* ln1_g =(const float*)d_in[2];
  const float* ln1_b =(const float*)d_in[3];
  const float* w_qkv =(const float*)d_in[4];
  const float* w_out =(const float*)d_in[5];
  const float* b_out =(const float*)d_in[6];
  const float* ln2_g =(const float*)d_in[7];
  const float* ln2_b =(const float*)d_in[8];
  const float* w1    =(const float*)d_in[9];
  const float* b1    =(const float*)d_in[10];
  const float* w2    =(const float*)d_in[11];
  const float* b2    =(const float*)d_in[12];
  float* X = (float*)d_out;

  __half *hh, *qkvh, *oh, *ffh, *wqkvh, *wouth, *w1h, *w2h;
  cudaGetSymbolAddress((void**)&hh,    g_hh);
  cudaGetSymbolAddress((void**)&qkvh,  g_qkvh);
  cudaGetSymbolAddress((void**)&oh,    g_oh);
  cudaGetSymbolAddress((void**)&ffh,   g_ffh);
  cudaGetSymbolAddress((void**)&wqkvh, g_wqkvh);
  cudaGetSymbolAddress((void**)&wouth, g_wouth);
  cudaGetSymbolAddress((void**)&w1h,   g_w1h);
  cudaGetSymbolAddress((void**)&w2h,   g_w2h);

  copy_kernel<<<(NTOK*DIMM+255)/256, 256>>>(x, X, NTOK*DIMM);

  // weight conversions (fp32 -> fp16), once per launch
  {
    int n;
    n = NDEPTH*DIMM*3*DIMM/4; conv_half<<<(n+255)/256,256>>>(w_qkv, wqkvh, n);
    n = NDEPTH*DIMM*DIMM/4;   conv_half<<<(n+255)/256,256>>>(w_out, wouth, n);
    n = NDEPTH*DIMM*FFD/4;    conv_half<<<(n+255)/256,256>>>(w1,    w1h,   n);
    n = NDEPTH*FFD*DIMM/4;    conv_half<<<(n+255)/256,256>>>(w2,    w2h,   n);
  }

  for(int l=0;l<NDEPTH;l++){
    // ---- attention block ----
    layernorm_h<<<NTOK,256>>>(X, ln1_g + l*DIMM, ln1_b + l*DIMM, hh);
    gemm_h<0,__half><<<dim3(24,16),256>>>(
        hh, DIMM, wqkvh + (size_t)l*DIMM*3*DIMM, 3*DIMM,
        qkvh, 3*DIMM, nullptr, nullptr, NTOK, 3*DIMM, DIMM);
    attn_flash_h<<<dim3(16,NBATCH*NHEADS),128>>>(qkvh, rpb, oh);
    gemm_h<1,float><<<dim3(8,16),256>>>(
        oh, DIMM, wouth + (size_t)l*DIMM*DIMM, DIMM,
        X, DIMM, b_out + l*DIMM, X, NTOK, DIMM, DIMM);
    // ---- FFN block ----
    layernorm_h<<<NTOK,256>>>(X, ln2_g + l*DIMM, ln2_b + l*DIMM, hh);
    gemm_h<2,__half><<<dim3(32,16),256>>>(
        hh, DIMM, w1h + (size_t)l*DIMM*FFD, FFD,
        ffh, FFD, b1 + l*FFD, nullptr, NTOK, FFD, DIMM);
    gemm_h<1,float><<<dim3(8,16),256>>>(
        ffh, FFD, w2h + (size_t)l*FFD*DIMM, DIMM,
        X, DIMM, b2 + l*DIMM, X, NTOK, DIMM, FFD);
  }
}

// round 7
// speedup vs baseline: 6.8381x; 1.0845x over previous
#include <cuda_runtime.h>
#include <cuda_fp16.h>
#include <math.h>
#include <stdint.h>

#define SEQ    1024
#define DIMM   1024
#define NHEADS 16
#define FFD    4096
#define NBATCH 2
#define NTOK   (NBATCH*SEQ)
#define NDEPTH 6

// ---------------- scratch (allocation-free: __device__ globals) ----------------
__device__ __half g_hh[NTOK*DIMM];
__device__ __half g_qkvh[NTOK*3*DIMM];
__device__ __half g_oh[NTOK*DIMM];
__device__ __half g_ffh[NTOK*FFD];
__device__ __half g_wqkvh[(size_t)NDEPTH*DIMM*3*DIMM];
__device__ __half g_wouth[(size_t)NDEPTH*DIMM*DIMM];
__device__ __half g_w1h[(size_t)NDEPTH*DIMM*FFD];
__device__ __half g_w2h[(size_t)NDEPTH*FFD*DIMM];

// ---------------- ptx helpers ----------------
__device__ __forceinline__ uint32_t smem_u32(const void* p){
  uint32_t a;
  asm("{ .reg .u64 t; cvta.to.shared.u64 t, %1; cvt.u32.u64 %0, t; }" : "=r"(a) : "l"(p));
  return a;
}
__device__ __forceinline__ void mma16h(float* d, const uint32_t* a, const uint32_t* b){
  asm volatile("mma.sync.aligned.m16n8k16.row.col.f32.f16.f16.f32 "
    "{%0,%1,%2,%3}, {%4,%5,%6,%7}, {%8,%9}, {%0,%1,%2,%3};\n"
    : "+f"(d[0]),"+f"(d[1]),"+f"(d[2]),"+f"(d[3])
    : "r"(a[0]),"r"(a[1]),"r"(a[2]),"r"(a[3]),
      "r"(b[0]),"r"(b[1]));
}
__device__ __forceinline__ void ldm_x4(uint32_t* r, uint32_t addr){
  asm volatile("ldmatrix.sync.aligned.m8n8.x4.shared.b16 {%0,%1,%2,%3}, [%4];"
    : "=r"(r[0]),"=r"(r[1]),"=r"(r[2]),"=r"(r[3]) : "r"(addr));
}
__device__ __forceinline__ void ldm_x4t(uint32_t* r, uint32_t addr){
  asm volatile("ldmatrix.sync.aligned.m8n8.x4.trans.shared.b16 {%0,%1,%2,%3}, [%4];"
    : "=r"(r[0]),"=r"(r[1]),"=r"(r[2]),"=r"(r[3]) : "r"(addr));
}
__device__ __forceinline__ void cp16(uint32_t smem, const void* g){
  asm volatile("cp.async.cg.shared.global [%0], [%1], 16;" :: "r"(smem), "l"(g));
}
#define CP_COMMIT() asm volatile("cp.async.commit_group;" ::: "memory")
#define CP_WAIT0()  asm volatile("cp.async.wait_group 0;" ::: "memory")
#define CP_WAIT1()  asm volatile("cp.async.wait_group 1;" ::: "memory")
#define CP_WAIT2()  asm volatile("cp.async.wait_group 2;" ::: "memory")

__device__ __forceinline__ uint32_t packh2(float x, float y){
  __half2 h = __floats2half2_rn(x, y);
  return *(uint32_t*)&h;
}

// ---------------- block reductions (blockDim.x == 256) ----------------
__device__ __forceinline__ float blockReduceSum(float val, float* sh){
  #pragma unroll
  for(int o=16;o>0;o>>=1) val += __shfl_xor_sync(0xffffffffu, val, o);
  int wid = threadIdx.x>>5;
  __syncthreads();
  if((threadIdx.x&31)==0) sh[wid]=val;
  __syncthreads();
  float r = 0.f;
  #pragma unroll
  for(int w=0;w<8;w++) r += sh[w];
  return r;
}

// ---------------- small kernels ----------------
__global__ void copy_kernel(const float* __restrict__ src, float* __restrict__ dst, int n){
  int i = blockIdx.x*blockDim.x + threadIdx.x;
  if(i<n) dst[i]=src[i];
}

__global__ void conv_half(const float* __restrict__ src, __half* __restrict__ dst, int n4){
  int i = blockIdx.x*blockDim.x + threadIdx.x;
  if(i<n4){
    float4 v = ((const float4*)src)[i];
    uint2 u;
    u.x = packh2(v.x, v.y);
    u.y = packh2(v.z, v.w);
    ((uint2*)dst)[i] = u;
  }
}

__global__ void layernorm_h(const float* __restrict__ x, const float* __restrict__ g,
                            const float* __restrict__ beta, __half* __restrict__ out){
  __shared__ float sh[8];
  int row = blockIdx.x, t = threadIdx.x;
  const float4* xr = (const float4*)(x + (size_t)row*DIMM);
  float4 v = xr[t];
  float s = v.x+v.y+v.z+v.w;
  s = blockReduceSum(s, sh);
  float mu = s * (1.f/DIMM);
  float dx=v.x-mu, dy=v.y-mu, dz=v.z-mu, dw=v.w-mu;
  float ss = dx*dx+dy*dy+dz*dz+dw*dw;
  ss = blockReduceSum(ss, sh);
  float rinv = rsqrtf(ss*(1.f/DIMM) + 1e-5f);
  const float4 gg = ((const float4*)g)[t];
  const float4 bb = ((const float4*)beta)[t];
  uint2 u;
  u.x = packh2(dx*rinv*gg.x + bb.x, dy*rinv*gg.y + bb.y);
  u.y = packh2(dz*rinv*gg.z + bb.z, dw*rinv*gg.w + bb.w);
  ((uint2*)(out + (size_t)row*DIMM))[t] = u;
}

// ---------------- fp16 GEMM: cp.async 4-stage pipeline ----------------
// C[M,N] = A[M,K] @ B[K,N] (+ epilogue). 128x128x32 tile, 8 warps (2x4).
// EPI: 0=none(half out), 1=+bias+res(float out), 2=gelu(+bias)(half out)
#define APITCH 40
#define BPITCH 136
#define ASZ (128*APITCH)            // halves per A stage
#define BSZ (32*BPITCH)             // halves per B stage
#define STG (ASZ+BSZ)               // halves per stage
#define GH_SMEM (4*STG*2)           // bytes (4 stages)

template<int EPI, typename OT>
__global__ void __launch_bounds__(256)
gemm_h(const __half* __restrict__ A, int lda,
       const __half* __restrict__ B, int ldb,
       OT* __restrict__ C, int ldc,
       const float* __restrict__ bias, const float* __restrict__ res,
       int M, int N, int K)
{
  constexpr int MT=4, NT=4;
  extern __shared__ __half smh[];

  int t=threadIdx.x;
  const __half* Ag = A + (size_t)blockIdx.y*128*lda;
  const __half* Bg = B + blockIdx.x*128;

  float acc[MT][NT][4];
  #pragma unroll
  for(int i=0;i<MT;i++)
    #pragma unroll
    for(int j=0;j<NT;j++)
      #pragma unroll
      for(int r=0;r<4;r++) acc[i][j][r]=0.f;

  int wid=t>>5, lane=t&31;
  int wm=wid>>2, wn=wid&3;
  int m0=wm*64, n0=wn*32;
  int qr=lane>>2, rr=lane&3;

  uint32_t sbase = smem_u32(smh);
  uint32_t aoff = sbase + (uint32_t)(((m0 + (lane&15))*APITCH + (lane>>4)*8) * 2);
  uint32_t boff = sbase + (uint32_t)((ASZ + (lane&15)*BPITCH + n0 + (lane>>4)*8) * 2);

  const int KT = K >> 5;

  // tile loader: 4 cp16 per thread (A: 2, B: 2)
  auto load_tile = [&](int kt, int buf){
    __half* As = smh + buf*STG;
    __half* Bs = As + ASZ;
    const __half* Asrc = Ag + kt*32;
    #pragma unroll
    for(int i=0;i<2;i++){
      int c=t+256*i;
      cp16(smem_u32(As + (c>>2)*APITCH + ((c&3)<<3)),
           Asrc + (size_t)(c>>2)*lda + ((c&3)<<3));
    }
    const __half* Bsrc = Bg + (size_t)(kt*32)*ldb;
    #pragma unroll
    for(int i=0;i<2;i++){
      int c=t+256*i;
      cp16(smem_u32(Bs + (c>>4)*BPITCH + ((c&15)<<3)),
           Bsrc + (size_t)(c>>4)*ldb + ((c&15)<<3));
    }
  };

  // prologue: stages 0..2
  #pragma unroll
  for(int s=0;s<3;s++){ load_tile(s,s); CP_COMMIT(); }

  for(int kt=0;kt<KT;kt++){
    CP_WAIT2();
    __syncthreads();
    if(kt+3<KT) load_tile(kt+3,(kt+3)&3);
    CP_COMMIT();                       // empty groups in tail keep count stable
    uint32_t so = (uint32_t)(((kt&3)*STG)*2);
    #pragma unroll
    for(int ks=0;ks<2;ks++){
      uint32_t af[MT][4];
      #pragma unroll
      for(int mt=0;mt<MT;mt++)
        ldm_x4(af[mt], aoff + so + (uint32_t)((mt*16*APITCH + ks*16)*2));
      uint32_t bf[2][4];
      #pragma unroll
      for(int nh=0;nh<2;nh++)
        ldm_x4t(bf[nh], boff + so + (uint32_t)((ks*16*BPITCH + nh*16)*2));
      #pragma unroll
      for(int mt=0;mt<MT;mt++)
        #pragma unroll
        for(int nt=0;nt<NT;nt++)
          mma16h(acc[mt][nt], af[mt], &bf[nt>>1][(nt&1)*2]);
    }
  }

  int brow = blockIdx.y*128 + m0 + qr;
  int bcol = blockIdx.x*128 + n0 + (rr<<1);
  #pragma unroll
  for(int mt=0;mt<MT;mt++){
    #pragma unroll
    for(int nt=0;nt<NT;nt++){
      int col = bcol + nt*8;
      #pragma unroll
      for(int hh=0;hh<2;hh++){
        int row = brow + mt*16 + hh*8;
        float vx = acc[mt][nt][2*hh+0];
        float vy = acc[mt][nt][2*hh+1];
        if(EPI==1||EPI==2){ vx += bias[col]; vy += bias[col+1]; }
        if(EPI==2){
          vx = 0.5f*vx*(1.f+erff(vx*0.70710678118654752f));
          vy = 0.5f*vy*(1.f+erff(vy*0.70710678118654752f));
        }
        if(EPI==1){
          vx += res[(size_t)row*ldc+col];
          vy += res[(size_t)row*ldc+col+1];
        }
        if(sizeof(OT)==2){
          *(uint32_t*)((__half*)C + (size_t)row*ldc + col) = packh2(vx,vy);
        }else{
          float2 o; o.x=vx; o.y=vy;
          *(float2*)((float*)C + (size_t)row*ldc + col) = o;
        }
      }
    }
  }
}

// ---------------- fused flash attention, fp16 mma + cp.async (unchanged) ----------------
#define FPITCH 72

__global__ void __launch_bounds__(128)
attn_flash_h(const __half* __restrict__ qkv, const float* __restrict__ rpb,
             __half* __restrict__ O)
{
  __shared__ __half Qs[64*FPITCH];
  __shared__ __half Ks[2*64*FPITCH];
  __shared__ __half Vs[2*64*FPITCH];

  int t = threadIdx.x, lane = t&31, w = t>>5;
  int qr = lane>>2, rr = lane&3;
  int it = blockIdx.x, bh = blockIdx.y;
  int b = bh>>4, h = bh&15;
  const __half* Qg = qkv + (size_t)(b*SEQ + it*64)*(3*DIMM) + h*64;
  const __half* Kg = qkv + (size_t)b*SEQ*(3*DIMM) + DIMM   + h*64;
  const __half* Vg = qkv + (size_t)b*SEQ*(3*DIMM) + 2*DIMM + h*64;
  const float* Rg = rpb + ((size_t)h*SEQ + it*64)*SEQ;

  uint32_t sQ = smem_u32(Qs), sK = smem_u32(Ks), sV = smem_u32(Vs);

  #pragma unroll
  for(int u=0;u<4;u++){
    int c = t + 128*u;
    int row = c>>3, cc = c&7;
    cp16(sQ + (uint32_t)(row*FPITCH + cc*8)*2, Qg + (size_t)row*(3*DIMM) + cc*8);
  }
  #pragma unroll
  for(int u=0;u<8;u++){
    int c = t + 128*u;
    int mat = c>>9, row=(c>>3)&63, cc=c&7;
    const __half* src = (mat? Vg:Kg) + (size_t)row*(3*DIMM) + cc*8;
    uint32_t dst = (mat? sV:sK) + (uint32_t)(row*FPITCH + cc*8)*2;
    cp16(dst, src);
  }
  CP_COMMIT();
  #pragma unroll
  for(int u=0;u<8;u++){
    int c = t + 128*u;
    int mat = c>>9, row=(c>>3)&63, cc=c&7;
    const __half* src = (mat? Vg:Kg) + (size_t)(64+row)*(3*DIMM) + cc*8;
    uint32_t dst = (mat? sV:sK) + (uint32_t)(64*FPITCH + row*FPITCH + cc*8)*2;
    cp16(dst, src);
  }
  CP_COMMIT();

  int m0 = w*16;
  uint32_t a_base  = sQ + (uint32_t)(((m0 + (lane&15))*FPITCH + (lane>>4)*8)*2);
  uint32_t k_lbase = (uint32_t)((((lane&7) + ((lane&16)?8:0))*FPITCH + ((lane&8)?8:0))*2);
  uint32_t v_lbase = (uint32_t)(((lane&15)*FPITCH + (lane>>4)*8)*2);

  uint32_t qf[4][4];
  float oacc[8][4];
  #pragma unroll
  for(int nf=0;nf<8;nf++)
    #pragma unroll
    for(int r=0;r<4;r++) oacc[nf][r]=0.f;
  float mrow0=-1e30f, mrow1=-1e30f, lrow0=0.f, lrow1=0.f;

  for(int jt=0;jt<16;jt++){
    if(jt<15) CP_WAIT1(); else CP_WAIT0();
    __syncthreads();
    if(jt==0){
      #pragma unroll
      for(int kb=0;kb<4;kb++) ldm_x4(qf[kb], a_base + (uint32_t)(kb*16*2));
    }
    uint32_t bufK = sK + (uint32_t)((jt&1)*64*FPITCH*2);
    uint32_t bufV = sV + (uint32_t)((jt&1)*64*FPITCH*2);

    float s[8][4];
    #pragma unroll
    for(int nf=0;nf<8;nf++)
      #pragma unroll
      for(int r=0;r<4;r++) s[nf][r]=0.f;
    #pragma unroll
    for(int kb=0;kb<4;kb++){
      #pragma unroll
      for(int jnp=0;jnp<4;jnp++){
        uint32_t kr[4];
        ldm_x4(kr, bufK + k_lbase + (uint32_t)((jnp*16*FPITCH + kb*16)*2));
        mma16h(s[2*jnp  ], qf[kb], kr);
        mma16h(s[2*jnp+1], qf[kb], kr+2);
      }
    }
    #pragma unroll
    for(int nf=0;nf<8;nf++){
      const float* rp = Rg + (size_t)(m0+qr)*SEQ + jt*64 + nf*8 + 2*rr;
      float2 r0 = *(const float2*)rp;
      float2 r1 = *(const float2*)(rp + 8*SEQ);
      s[nf][0]=fmaf(s[nf][0],0.125f,r0.x);
      s[nf][1]=fmaf(s[nf][1],0.125f,r0.y);
      s[nf][2]=fmaf(s[nf][2],0.125f,r1.x);
      s[nf][3]=fmaf(s[nf][3],0.125f,r1.y);
    }
    float mx0=-1e30f, mx1=-1e30f;
    #pragma unroll
    for(int nf=0;nf<8;nf++){
      mx0=fmaxf(mx0,fmaxf(s[nf][0],s[nf][1]));
      mx1=fmaxf(mx1,fmaxf(s[nf][2],s[nf][3]));
    }
    mx0=fmaxf(mx0,__shfl_xor_sync(0xffffffffu,mx0,1));
    mx0=fmaxf(mx0,__shfl_xor_sync(0xffffffffu,mx0,2));
    mx1=fmaxf(mx1,__shfl_xor_sync(0xffffffffu,mx1,1));
    mx1=fmaxf(mx1,__shfl_xor_sync(0xffffffffu,mx1,2));
    float mn0=fmaxf(mrow0,mx0), mn1=fmaxf(mrow1,mx1);
    float a0=__expf(mrow0-mn0), a1=__expf(mrow1-mn1);
    mrow0=mn0; mrow1=mn1;
    float sum0=0.f, sum1=0.f;
    #pragma unroll
    for(int nf=0;nf<8;nf++){
      s[nf][0]=__expf(s[nf][0]-mn0); s[nf][1]=__expf(s[nf][1]-mn0);
      s[nf][2]=__expf(s[nf][2]-mn1); s[nf][3]=__expf(s[nf][3]-mn1);
      sum0 += s[nf][0]+s[nf][1];
      sum1 += s[nf][2]+s[nf][3];
    }
    sum0 += __shfl_xor_sync(0xffffffffu,sum0,1);
    sum0 += __shfl_xor_sync(0xffffffffu,sum0,2);
    sum1 += __shfl_xor_sync(0xffffffffu,sum1,1);
    sum1 += __shfl_xor_sync(0xffffffffu,sum1,2);
    lrow0 = lrow0*a0 + sum0;
    lrow1 = lrow1*a1 + sum1;
    #pragma unroll
    for(int nf=0;nf<8;nf++){
      oacc[nf][0]*=a0; oacc[nf][1]*=a0;
      oacc[nf][2]*=a1; oacc[nf][3]*=a1;
    }
    uint32_t pf[4][4];
    #pragma unroll
    for(int kb=0;kb<4;kb++){
      pf[kb][0]=packh2(s[2*kb  ][0], s[2*kb  ][1]);
      pf[kb][1]=packh2(s[2*kb  ][2], s[2*kb  ][3]);
      pf[kb][2]=packh2(s[2*kb+1][0], s[2*kb+1][1]);
      pf[kb][3]=packh2(s[2*kb+1][2], s[2*kb+1][3]);
    }
    #pragma unroll
    for(int kb=0;kb<4;kb++){
      #pragma unroll
      for(int nfp=0;nfp<4;nfp++){
        uint32_t vr[4];
        ldm_x4t(vr, bufV + v_lbase + (uint32_t)((kb*16*FPITCH + nfp*16)*2));
        mma16h(oacc[2*nfp  ], pf[kb], vr);
        mma16h(oacc[2*nfp+1], pf[kb], vr+2);
      }
    }
    __syncthreads();
    if(jt<14){
      int nt = jt+2, buf = jt&1;
      #pragma unroll
      for(int u=0;u<8;u++){
        int c = t + 128*u;
        int mat = c>>9, row=(c>>3)&63, cc=c&7;
        const __half* src = (mat? Vg:Kg) + (size_t)(nt*64+row)*(3*DIMM) + cc*8;
        uint32_t dst = (mat? sV:sK) + (uint32_t)(buf*64*FPITCH + row*FPITCH + cc*8)*2;
        cp16(dst, src);
      }
      CP_COMMIT();
    }
  }

  float inv0=1.f/lrow0, inv1=1.f/lrow1;
  __half* Ob = O + (size_t)(b*SEQ + it*64)*DIMM + h*64;
  #pragma unroll
  for(int nf=0;nf<8;nf++){
    *(uint32_t*)(Ob + (size_t)(m0+qr  )*DIMM + nf*8+2*rr) = packh2(oacc[nf][0]*inv0, oacc[nf][1]*inv0);
    *(uint32_t*)(Ob + (size_t)(m0+qr+8)*DIMM + nf*8+2*rr) = packh2(oacc[nf][2]*inv1, oacc[nf][3]*inv1);
  }
}

// ---------------- driver ----------------
extern "C" void kernel_launch(void* const* d_in, const int* in_sizes, int n_in,
                              void* d_out, int out_size){
  const float* x     =(const float*)d_in[0];
  const float* rpb   =(const float*)d_in[1];
  const float* ln1_g =(const float*)d_in[2];
  const float* ln1_b =(const float*)d_in[3];
  const float* w_qkv =(const float*)d_in[4];
  const float* w_out =(const float*)d_in[5];
  const float* b_out =(const float*)d_in[6];
  const float* ln2_g =(const float*)d_in[7];
  const float* ln2_b =(const float*)d_in[8];
  const float* w1    =(const float*)d_in[9];
  const float* b1    =(const float*)d_in[10];
  const float* w2    =(const float*)d_in[11];
  const float* b2    =(const float*)d_in[12];
  float* X = (float*)d_out;

  __half *hh, *qkvh, *oh, *ffh, *wqkvh, *wouth, *w1h, *w2h;
  cudaGetSymbolAddress((void**)&hh,    g_hh);
  cudaGetSymbolAddress((void**)&qkvh,  g_qkvh);
  cudaGetSymbolAddress((void**)&oh,    g_oh);
  cudaGetSymbolAddress((void**)&ffh,   g_ffh);
  cudaGetSymbolAddress((void**)&wqkvh, g_wqkvh);
  cudaGetSymbolAddress((void**)&wouth, g_wouth);
  cudaGetSymbolAddress((void**)&w1h,   g_w1h);
  cudaGetSymbolAddress((void**)&w2h,   g_w2h);

  cudaFuncSetAttribute(gemm_h<0,__half>, cudaFuncAttributeMaxDynamicSharedMemorySize, GH_SMEM);
  cudaFuncSetAttribute(gemm_h<1,float>,  cudaFuncAttributeMaxDynamicSharedMemorySize, GH_SMEM);
  cudaFuncSetAttribute(gemm_h<2,__half>, cudaFuncAttributeMaxDynamicSharedMemorySize, GH_SMEM);

  copy_kernel<<<(NTOK*DIMM+255)/256, 256>>>(x, X, NTOK*DIMM);

  {
    int n;
    n = NDEPTH*DIMM*3*DIMM/4; conv_half<<<(n+255)/256,256>>>(w_qkv, wqkvh, n);
    n = NDEPTH*DIMM*DIMM/4;   conv_half<<<(n+255)/256,256>>>(w_out, wouth, n);
    n = NDEPTH*DIMM*FFD/4;    conv_half<<<(n+255)/256,256>>>(w1,    w1h,   n);
    n = NDEPTH*FFD*DIMM/4;    conv_half<<<(n+255)/256,256>>>(w2,    w2h,   n);
  }

  for(int l=0;l<NDEPTH;l++){
    // ---- attention block ----
    layernorm_h<<<NTOK,256>>>(X, ln1_g + l*DIMM, ln1_b + l*DIMM, hh);
    gemm_h<0,__half><<<dim3(24,16),256,GH_SMEM>>>(
        hh, DIMM, wqkvh + (size_t)l*DIMM*3*DIMM, 3*DIMM,
        qkvh, 3*DIMM, nullptr, nullptr, NTOK, 3*DIMM, DIMM);
    attn_flash_h<<<dim3(16,NBATCH*NHEADS),128>>>(qkvh, rpb, oh);
    gemm_h<1,float><<<dim3(8,16),256,GH_SMEM>>>(
        oh, DIMM, wouth + (size_t)l*DIMM*DIMM, DIMM,
        X, DIMM, b_out + l*DIMM, X, NTOK, DIMM, DIMM);
    // ---- FFN block ----
    layernorm_h<<<NTOK,256>>>(X, ln2_g + l*DIMM, ln2_b + l*DIMM, hh);
    gemm_h<2,__half><<<dim3(32,16),256,GH_SMEM>>>(
        hh, DIMM, w1h + (size_t)l*DIMM*FFD, FFD,
        ffh, FFD, b1 + l*FFD, nullptr, NTOK, FFD, DIMM);
    gemm_h<1,float><<<dim3(8,16),256,GH_SMEM>>>(
        ffh, FFD, w2h + (size_t)l*FFD*DIMM, DIMM,
        X, DIMM, b2 + l*DIMM, X, NTOK, DIMM, FFD);
  }
}

// round 8
// speedup vs baseline: 6.9058x; 1.0099x over previous
#include <cuda_runtime.h>
#include <cuda_fp16.h>
#include <math.h>
#include <stdint.h>

#define SEQ    1024
#define DIMM   1024
#define NHEADS 16
#define FFD    4096
#define NBATCH 2
#define NTOK   (NBATCH*SEQ)
#define NDEPTH 6

// ---------------- scratch (allocation-free: __device__ globals) ----------------
__device__ __half g_hh[NTOK*DIMM];
__device__ __half g_qkvh[NTOK*3*DIMM];
__device__ __half g_oh[NTOK*DIMM];
__device__ __half g_ffh[NTOK*FFD];
__device__ __half g_wqkvh[(size_t)NDEPTH*DIMM*3*DIMM];
__device__ __half g_wouth[(size_t)NDEPTH*DIMM*DIMM];
__device__ __half g_w1h[(size_t)NDEPTH*DIMM*FFD];
__device__ __half g_w2h[(size_t)NDEPTH*FFD*DIMM];
__device__ __half g_rpbh[(size_t)NHEADS*SEQ*SEQ];   // 32 MB

// ---------------- ptx helpers ----------------
__device__ __forceinline__ uint32_t smem_u32(const void* p){
  uint32_t a;
  asm("{ .reg .u64 t; cvta.to.shared.u64 t, %1; cvt.u32.u64 %0, t; }" : "=r"(a) : "l"(p));
  return a;
}
__device__ __forceinline__ void mma16h(float* d, const uint32_t* a, const uint32_t* b){
  asm volatile("mma.sync.aligned.m16n8k16.row.col.f32.f16.f16.f32 "
    "{%0,%1,%2,%3}, {%4,%5,%6,%7}, {%8,%9}, {%0,%1,%2,%3};\n"
    : "+f"(d[0]),"+f"(d[1]),"+f"(d[2]),"+f"(d[3])
    : "r"(a[0]),"r"(a[1]),"r"(a[2]),"r"(a[3]),
      "r"(b[0]),"r"(b[1]));
}
__device__ __forceinline__ void ldm_x4(uint32_t* r, uint32_t addr){
  asm volatile("ldmatrix.sync.aligned.m8n8.x4.shared.b16 {%0,%1,%2,%3}, [%4];"
    : "=r"(r[0]),"=r"(r[1]),"=r"(r[2]),"=r"(r[3]) : "r"(addr));
}
__device__ __forceinline__ void ldm_x4t(uint32_t* r, uint32_t addr){
  asm volatile("ldmatrix.sync.aligned.m8n8.x4.trans.shared.b16 {%0,%1,%2,%3}, [%4];"
    : "=r"(r[0]),"=r"(r[1]),"=r"(r[2]),"=r"(r[3]) : "r"(addr));
}
__device__ __forceinline__ void cp16(uint32_t smem, const void* g){
  asm volatile("cp.async.cg.shared.global [%0], [%1], 16;" :: "r"(smem), "l"(g));
}
#define CP_COMMIT() asm volatile("cp.async.commit_group;" ::: "memory")
#define CP_WAIT0()  asm volatile("cp.async.wait_group 0;" ::: "memory")
#define CP_WAIT1()  asm volatile("cp.async.wait_group 1;" ::: "memory")
#define CP_WAIT2()  asm volatile("cp.async.wait_group 2;" ::: "memory")

__device__ __forceinline__ uint32_t packh2(float x, float y){
  __half2 h = __floats2half2_rn(x, y);
  return *(uint32_t*)&h;
}

// ---------------- block reductions (blockDim.x == 256) ----------------
__device__ __forceinline__ float blockReduceSum(float val, float* sh){
  #pragma unroll
  for(int o=16;o>0;o>>=1) val += __shfl_xor_sync(0xffffffffu, val, o);
  int wid = threadIdx.x>>5;
  __syncthreads();
  if((threadIdx.x&31)==0) sh[wid]=val;
  __syncthreads();
  float r = 0.f;
  #pragma unroll
  for(int w=0;w<8;w++) r += sh[w];
  return r;
}

// ---------------- small kernels ----------------
__global__ void copy_kernel(const float* __restrict__ src, float* __restrict__ dst, int n){
  int i = blockIdx.x*blockDim.x + threadIdx.x;
  if(i<n) dst[i]=src[i];
}

__global__ void conv_half(const float* __restrict__ src, __half* __restrict__ dst, int n4){
  int i = blockIdx.x*blockDim.x + threadIdx.x;
  if(i<n4){
    float4 v = ((const float4*)src)[i];
    uint2 u;
    u.x = packh2(v.x, v.y);
    u.y = packh2(v.z, v.w);
    ((uint2*)dst)[i] = u;
  }
}

__global__ void layernorm_h(const float* __restrict__ x, const float* __restrict__ g,
                            const float* __restrict__ beta, __half* __restrict__ out){
  __shared__ float sh[8];
  int row = blockIdx.x, t = threadIdx.x;
  const float4* xr = (const float4*)(x + (size_t)row*DIMM);
  float4 v = xr[t];
  float s = v.x+v.y+v.z+v.w;
  s = blockReduceSum(s, sh);
  float mu = s * (1.f/DIMM);
  float dx=v.x-mu, dy=v.y-mu, dz=v.z-mu, dw=v.w-mu;
  float ss = dx*dx+dy*dy+dz*dz+dw*dw;
  ss = blockReduceSum(ss, sh);
  float rinv = rsqrtf(ss*(1.f/DIMM) + 1e-5f);
  const float4 gg = ((const float4*)g)[t];
  const float4 bb = ((const float4*)beta)[t];
  uint2 u;
  u.x = packh2(dx*rinv*gg.x + bb.x, dy*rinv*gg.y + bb.y);
  u.y = packh2(dz*rinv*gg.z + bb.z, dw*rinv*gg.w + bb.w);
  ((uint2*)(out + (size_t)row*DIMM))[t] = u;
}

// ---------------- fp16 GEMM: cp.async 4-stage pipeline ----------------
#define APITCH 40
#define BPITCH 136
#define ASZ (128*APITCH)
#define BSZ (32*BPITCH)
#define STG (ASZ+BSZ)
#define GH_SMEM (4*STG*2)

template<int EPI, typename OT>
__global__ void __launch_bounds__(256)
gemm_h(const __half* __restrict__ A, int lda,
       const __half* __restrict__ B, int ldb,
       OT* __restrict__ C, int ldc,
       const float* __restrict__ bias, const float* __restrict__ res,
       int M, int N, int K)
{
  constexpr int MT=4, NT=4;
  extern __shared__ __half smh[];

  int t=threadIdx.x;
  const __half* Ag = A + (size_t)blockIdx.y*128*lda;
  const __half* Bg = B + blockIdx.x*128;

  float acc[MT][NT][4];
  #pragma unroll
  for(int i=0;i<MT;i++)
    #pragma unroll
    for(int j=0;j<NT;j++)
      #pragma unroll
      for(int r=0;r<4;r++) acc[i][j][r]=0.f;

  int wid=t>>5, lane=t&31;
  int wm=wid>>2, wn=wid&3;
  int m0=wm*64, n0=wn*32;
  int qr=lane>>2, rr=lane&3;

  uint32_t sbase = smem_u32(smh);
  uint32_t aoff = sbase + (uint32_t)(((m0 + (lane&15))*APITCH + (lane>>4)*8) * 2);
  uint32_t boff = sbase + (uint32_t)((ASZ + (lane&15)*BPITCH + n0 + (lane>>4)*8) * 2);

  const int KT = K >> 5;

  auto load_tile = [&](int kt, int buf){
    __half* As = smh + buf*STG;
    __half* Bs = As + ASZ;
    const __half* Asrc = Ag + kt*32;
    #pragma unroll
    for(int i=0;i<2;i++){
      int c=t+256*i;
      cp16(smem_u32(As + (c>>2)*APITCH + ((c&3)<<3)),
           Asrc + (size_t)(c>>2)*lda + ((c&3)<<3));
    }
    const __half* Bsrc = Bg + (size_t)(kt*32)*ldb;
    #pragma unroll
    for(int i=0;i<2;i++){
      int c=t+256*i;
      cp16(smem_u32(Bs + (c>>4)*BPITCH + ((c&15)<<3)),
           Bsrc + (size_t)(c>>4)*ldb + ((c&15)<<3));
    }
  };

  #pragma unroll
  for(int s=0;s<3;s++){ load_tile(s,s); CP_COMMIT(); }

  for(int kt=0;kt<KT;kt++){
    CP_WAIT2();
    __syncthreads();
    if(kt+3<KT) load_tile(kt+3,(kt+3)&3);
    CP_COMMIT();
    uint32_t so = (uint32_t)(((kt&3)*STG)*2);
    #pragma unroll
    for(int ks=0;ks<2;ks++){
      uint32_t af[MT][4];
      #pragma unroll
      for(int mt=0;mt<MT;mt++)
        ldm_x4(af[mt], aoff + so + (uint32_t)((mt*16*APITCH + ks*16)*2));
      uint32_t bf[2][4];
      #pragma unroll
      for(int nh=0;nh<2;nh++)
        ldm_x4t(bf[nh], boff + so + (uint32_t)((ks*16*BPITCH + nh*16)*2));
      #pragma unroll
      for(int mt=0;mt<MT;mt++)
        #pragma unroll
        for(int nt=0;nt<NT;nt++)
          mma16h(acc[mt][nt], af[mt], &bf[nt>>1][(nt&1)*2]);
    }
  }

  int brow = blockIdx.y*128 + m0 + qr;
  int bcol = blockIdx.x*128 + n0 + (rr<<1);
  #pragma unroll
  for(int mt=0;mt<MT;mt++){
    #pragma unroll
    for(int nt=0;nt<NT;nt++){
      int col = bcol + nt*8;
      #pragma unroll
      for(int hh=0;hh<2;hh++){
        int row = brow + mt*16 + hh*8;
        float vx = acc[mt][nt][2*hh+0];
        float vy = acc[mt][nt][2*hh+1];
        if(EPI==1||EPI==2){ vx += bias[col]; vy += bias[col+1]; }
        if(EPI==2){
          vx = 0.5f*vx*(1.f+erff(vx*0.70710678118654752f));
          vy = 0.5f*vy*(1.f+erff(vy*0.70710678118654752f));
        }
        if(EPI==1){
          vx += res[(size_t)row*ldc+col];
          vy += res[(size_t)row*ldc+col+1];
        }
        if(sizeof(OT)==2){
          *(uint32_t*)((__half*)C + (size_t)row*ldc + col) = packh2(vx,vy);
        }else{
          float2 o; o.x=vx; o.y=vy;
          *(float2*)((float*)C + (size_t)row*ldc + col) = o;
        }
      }
    }
  }
}

// ---------------- fused flash attention: fp16 mma + cp.async + rpb prefetch ----------------
#define FPITCH 72

__global__ void __launch_bounds__(128)
attn_flash_h(const __half* __restrict__ qkv, const __half* __restrict__ rpb,
             __half* __restrict__ O)
{
  __shared__ __half Qs[64*FPITCH];
  __shared__ __half Ks[2*64*FPITCH];
  __shared__ __half Vs[2*64*FPITCH];

  int t = threadIdx.x, lane = t&31, w = t>>5;
  int qr = lane>>2, rr = lane&3;
  int it = blockIdx.x, bh = blockIdx.y;
  int b = bh>>4, h = bh&15;
  const __half* Qg = qkv + (size_t)(b*SEQ + it*64)*(3*DIMM) + h*64;
  const __half* Kg = qkv + (size_t)b*SEQ*(3*DIMM) + DIMM   + h*64;
  const __half* Vg = qkv + (size_t)b*SEQ*(3*DIMM) + 2*DIMM + h*64;

  uint32_t sQ = smem_u32(Qs), sK = smem_u32(Ks), sV = smem_u32(Vs);

  #pragma unroll
  for(int u=0;u<4;u++){
    int c = t + 128*u;
    int row = c>>3, cc = c&7;
    cp16(sQ + (uint32_t)(row*FPITCH + cc*8)*2, Qg + (size_t)row*(3*DIMM) + cc*8);
  }
  #pragma unroll
  for(int u=0;u<8;u++){
    int c = t + 128*u;
    int mat = c>>9, row=(c>>3)&63, cc=c&7;
    const __half* src = (mat? Vg:Kg) + (size_t)row*(3*DIMM) + cc*8;
    uint32_t dst = (mat? sV:sK) + (uint32_t)(row*FPITCH + cc*8)*2;
    cp16(dst, src);
  }
  CP_COMMIT();
  #pragma unroll
  for(int u=0;u<8;u++){
    int c = t + 128*u;
    int mat = c>>9, row=(c>>3)&63, cc=c&7;
    const __half* src = (mat? Vg:Kg) + (size_t)(64+row)*(3*DIMM) + cc*8;
    uint32_t dst = (mat? sV:sK) + (uint32_t)(64*FPITCH + row*FPITCH + cc*8)*2;
    cp16(dst, src);
  }
  CP_COMMIT();

  int m0 = w*16;
  // rpb row pointer for this thread (fp16)
  const __half* Rg = rpb + ((size_t)h*SEQ + it*64 + m0 + qr)*SEQ + 2*rr;

  uint32_t a_base  = sQ + (uint32_t)(((m0 + (lane&15))*FPITCH + (lane>>4)*8)*2);
  uint32_t k_lbase = (uint32_t)((((lane&7) + ((lane&16)?8:0))*FPITCH + ((lane&8)?8:0))*2);
  uint32_t v_lbase = (uint32_t)(((lane&15)*FPITCH + (lane>>4)*8)*2);

  uint32_t qf[4][4];
  float oacc[8][4];
  #pragma unroll
  for(int nf=0;nf<8;nf++)
    #pragma unroll
    for(int r=0;r<4;r++) oacc[nf][r]=0.f;
  float mrow0=-1e30f, mrow1=-1e30f, lrow0=0.f, lrow1=0.f;

  for(int jt=0;jt<16;jt++){
    if(jt<15) CP_WAIT1(); else CP_WAIT0();
    __syncthreads();
    if(jt==0){
      #pragma unroll
      for(int kb=0;kb<4;kb++) ldm_x4(qf[kb], a_base + (uint32_t)(kb*16*2));
    }
    uint32_t bufK = sK + (uint32_t)((jt&1)*64*FPITCH*2);
    uint32_t bufV = sV + (uint32_t)((jt&1)*64*FPITCH*2);

    // ---- prefetch rpb fragments (hide gmem latency behind QK mma) ----
    uint32_t rpf[8][2];
    {
      const __half* rp = Rg + jt*64;
      #pragma unroll
      for(int nf=0;nf<8;nf++){
        rpf[nf][0] = *(const uint32_t*)(rp + nf*8);
        rpf[nf][1] = *(const uint32_t*)(rp + 8*SEQ + nf*8);
      }
    }

    // ---- S = Q K^T ----
    float s[8][4];
    #pragma unroll
    for(int nf=0;nf<8;nf++)
      #pragma unroll
      for(int r=0;r<4;r++) s[nf][r]=0.f;
    #pragma unroll
    for(int kb=0;kb<4;kb++){
      #pragma unroll
      for(int jnp=0;jnp<4;jnp++){
        uint32_t kr[4];
        ldm_x4(kr, bufK + k_lbase + (uint32_t)((jnp*16*FPITCH + kb*16)*2));
        mma16h(s[2*jnp  ], qf[kb], kr);
        mma16h(s[2*jnp+1], qf[kb], kr+2);
      }
    }
    // ---- scale + rpb (from prefetched registers) ----
    #pragma unroll
    for(int nf=0;nf<8;nf++){
      float2 r0 = __half22float2(*(__half2*)&rpf[nf][0]);
      float2 r1 = __half22float2(*(__half2*)&rpf[nf][1]);
      s[nf][0]=fmaf(s[nf][0],0.125f,r0.x);
      s[nf][1]=fmaf(s[nf][1],0.125f,r0.y);
      s[nf][2]=fmaf(s[nf][2],0.125f,r1.x);
      s[nf][3]=fmaf(s[nf][3],0.125f,r1.y);
    }
    // ---- online softmax ----
    float mx0=-1e30f, mx1=-1e30f;
    #pragma unroll
    for(int nf=0;nf<8;nf++){
      mx0=fmaxf(mx0,fmaxf(s[nf][0],s[nf][1]));
      mx1=fmaxf(mx1,fmaxf(s[nf][2],s[nf][3]));
    }
    mx0=fmaxf(mx0,__shfl_xor_sync(0xffffffffu,mx0,1));
    mx0=fmaxf(mx0,__shfl_xor_sync(0xffffffffu,mx0,2));
    mx1=fmaxf(mx1,__shfl_xor_sync(0xffffffffu,mx1,1));
    mx1=fmaxf(mx1,__shfl_xor_sync(0xffffffffu,mx1,2));
    float mn0=fmaxf(mrow0,mx0), mn1=fmaxf(mrow1,mx1);
    float a0=__expf(mrow0-mn0), a1=__expf(mrow1-mn1);
    mrow0=mn0; mrow1=mn1;
    float sum0=0.f, sum1=0.f;
    #pragma unroll
    for(int nf=0;nf<8;nf++){
      s[nf][0]=__expf(s[nf][0]-mn0); s[nf][1]=__expf(s[nf][1]-mn0);
      s[nf][2]=__expf(s[nf][2]-mn1); s[nf][3]=__expf(s[nf][3]-mn1);
      sum0 += s[nf][0]+s[nf][1];
      sum1 += s[nf][2]+s[nf][3];
    }
    sum0 += __shfl_xor_sync(0xffffffffu,sum0,1);
    sum0 += __shfl_xor_sync(0xffffffffu,sum0,2);
    sum1 += __shfl_xor_sync(0xffffffffu,sum1,1);
    sum1 += __shfl_xor_sync(0xffffffffu,sum1,2);
    lrow0 = lrow0*a0 + sum0;
    lrow1 = lrow1*a1 + sum1;
    #pragma unroll
    for(int nf=0;nf<8;nf++){
      oacc[nf][0]*=a0; oacc[nf][1]*=a0;
      oacc[nf][2]*=a1; oacc[nf][3]*=a1;
    }
    uint32_t pf[4][4];
    #pragma unroll
    for(int kb=0;kb<4;kb++){
      pf[kb][0]=packh2(s[2*kb  ][0], s[2*kb  ][1]);
      pf[kb][1]=packh2(s[2*kb  ][2], s[2*kb  ][3]);
      pf[kb][2]=packh2(s[2*kb+1][0], s[2*kb+1][1]);
      pf[kb][3]=packh2(s[2*kb+1][2], s[2*kb+1][3]);
    }
    #pragma unroll
    for(int kb=0;kb<4;kb++){
      #pragma unroll
      for(int nfp=0;nfp<4;nfp++){
        uint32_t vr[4];
        ldm_x4t(vr, bufV + v_lbase + (uint32_t)((kb*16*FPITCH + nfp*16)*2));
        mma16h(oacc[2*nfp  ], pf[kb], vr);
        mma16h(oacc[2*nfp+1], pf[kb], vr+2);
      }
    }
    __syncthreads();
    if(jt<14){
      int nt = jt+2, buf = jt&1;
      #pragma unroll
      for(int u=0;u<8;u++){
        int c = t + 128*u;
        int mat = c>>9, row=(c>>3)&63, cc=c&7;
        const __half* src = (mat? Vg:Kg) + (size_t)(nt*64+row)*(3*DIMM) + cc*8;
        uint32_t dst = (mat? sV:sK) + (uint32_t)(buf*64*FPITCH + row*FPITCH + cc*8)*2;
        cp16(dst, src);
      }
      CP_COMMIT();
    }
  }

  float inv0=1.f/lrow0, inv1=1.f/lrow1;
  __half* Ob = O + (size_t)(b*SEQ + it*64)*DIMM + h*64;
  #pragma unroll
  for(int nf=0;nf<8;nf++){
    *(uint32_t*)(Ob + (size_t)(m0+qr  )*DIMM + nf*8+2*rr) = packh2(oacc[nf][0]*inv0, oacc[nf][1]*inv0);
    *(uint32_t*)(Ob + (size_t)(m0+qr+8)*DIMM + nf*8+2*rr) = packh2(oacc[nf][2]*inv1, oacc[nf][3]*inv1);
  }
}

// ---------------- driver ----------------
extern "C" void kernel_launch(void* const* d_in, const int* in_sizes, int n_in,
                              void* d_out, int out_size){
  const float* x     =(const float*)d_in[0];
  const float* rpb   =(const float*)d_in[1];
  const float* ln1_g =(const float*)d_in[2];
  const float* ln1_b =(const float*)d_in[3];
  const float* w_qkv =(const float*)d_in[4];
  const float* w_out =(const float*)d_in[5];
  const float* b_out =(const float*)d_in[6];
  const float* ln2_g =(const float*)d_in[7];
  const float* ln2_b =(const float*)d_in[8];
  const float* w1    =(const float*)d_in[9];
  const float* b1    =(const float*)d_in[10];
  const float* w2    =(const float*)d_in[11];
  const float* b2    =(const float*)d_in[12];
  float* X = (float*)d_out;

  __half *hh, *qkvh, *oh, *ffh, *wqkvh, *wouth, *w1h, *w2h, *rpbh;
  cudaGetSymbolAddress((void**)&hh,    g_hh);
  cudaGetSymbolAddress((void**)&qkvh,  g_qkvh);
  cudaGetSymbolAddress((void**)&oh,    g_oh);
  cudaGetSymbolAddress((void**)&ffh,   g_ffh);
  cudaGetSymbolAddress((void**)&wqkvh, g_wqkvh);
  cudaGetSymbolAddress((void**)&wouth, g_wouth);
  cudaGetSymbolAddress((void**)&w1h,   g_w1h);
  cudaGetSymbolAddress((void**)&w2h,   g_w2h);
  cudaGetSymbolAddress((void**)&rpbh,  g_rpbh);

  cudaFuncSetAttribute(gemm_h<0,__half>, cudaFuncAttributeMaxDynamicSharedMemorySize, GH_SMEM);
  cudaFuncSetAttribute(gemm_h<1,float>,  cudaFuncAttributeMaxDynamicSharedMemorySize, GH_SMEM);
  cudaFuncSetAttribute(gemm_h<2,__half>, cudaFuncAttributeMaxDynamicSharedMemorySize, GH_SMEM);

  copy_kernel<<<(NTOK*DIMM+255)/256, 256>>>(x, X, NTOK*DIMM);

  {
    int n;
    n = NDEPTH*DIMM*3*DIMM/4;   conv_half<<<(n+255)/256,256>>>(w_qkv, wqkvh, n);
    n = NDEPTH*DIMM*DIMM/4;     conv_half<<<(n+255)/256,256>>>(w_out, wouth, n);
    n = NDEPTH*DIMM*FFD/4;      conv_half<<<(n+255)/256,256>>>(w1,    w1h,   n);
    n = NDEPTH*FFD*DIMM/4;      conv_half<<<(n+255)/256,256>>>(w2,    w2h,   n);
    n = NHEADS*SEQ*SEQ/4;       conv_half<<<(n+255)/256,256>>>(rpb,   rpbh,  n);
  }

  for(int l=0;l<NDEPTH;l++){
    // ---- attention block ----
    layernorm_h<<<NTOK,256>>>(X, ln1_g + l*DIMM, ln1_b + l*DIMM, hh);
    gemm_h<0,__half><<<dim3(24,16),256,GH_SMEM>>>(
        hh, DIMM, wqkvh + (size_t)l*DIMM*3*DIMM, 3*DIMM,
        qkvh, 3*DIMM, nullptr, nullptr, NTOK, 3*DIMM, DIMM);
    attn_flash_h<<<dim3(16,NBATCH*NHEADS),128>>>(qkvh, rpbh, oh);
    gemm_h<1,float><<<dim3(8,16),256,GH_SMEM>>>(
        oh, DIMM, wouth + (size_t)l*DIMM*DIMM, DIMM,
        X, DIMM, b_out + l*DIMM, X, NTOK, DIMM, DIMM);
    // ---- FFN block ----
    layernorm_h<<<NTOK,256>>>(X, ln2_g + l*DIMM, ln2_b + l*DIMM, hh);
    gemm_h<2,__half><<<dim3(32,16),256,GH_SMEM>>>(
        hh, DIMM, w1h + (size_t)l*DIMM*FFD, FFD,
        ffh, FFD, b1 + l*FFD, nullptr, NTOK, FFD, DIMM);
    gemm_h<1,float><<<dim3(8,16),256,GH_SMEM>>>(
        ffh, FFD, w2h + (size_t)l*FFD*DIMM, DIMM,
        X, DIMM, b2 + l*DIMM, X, NTOK, DIMM, FFD);
  }
}